// round 8
// baseline (speedup 1.0000x reference)
#include <cuda_runtime.h>
#include <cuda_bf16.h>
#include <cstdint>

#define CIN   128
#define COUT  128
#define KHW   9
#define NB    (CIN*COUT*KHW)   // 147456
#define ZD    256
#define BATCH 32
#define HW    32
#define HW2   (HW*HW)

// ---------------- scratch (device globals; no allocs allowed) ----------------
__device__ __align__(1024) float          g_Wk[BATCH * NB];                 // fp32 (b,s,f,uv)
__device__ __align__(1024) __nv_bfloat16  g_W2hi[BATCH * 9 * 128 * 128];    // (b,uv,f,s)
__device__ __align__(1024) __nv_bfloat16  g_W2lo[BATCH * 9 * 128 * 128];
__device__ __align__(1024) __nv_bfloat16  g_xhi[BATCH * 34 * 36 * 128];     // (b,row,col,s) padded, pad stays 0
__device__ __align__(1024) __nv_bfloat16  g_xlo[BATCH * 34 * 36 * 128];

// ---------------- helpers ----------------
__device__ __forceinline__ uint32_t smem_u32(const void* p) {
    uint32_t a;
    asm("{ .reg .u64 t; cvta.to.shared.u64 t, %1; cvt.u32.u64 %0, t; }" : "=r"(a) : "l"(p));
    return a;
}
__device__ __forceinline__ void cp16(uint32_t dst, const void* src) {
    asm volatile("cp.async.cg.shared.global [%0], [%1], 16;" :: "r"(dst), "l"(src) : "memory");
}
#define CP_COMMIT() asm volatile("cp.async.commit_group;" ::: "memory")

__device__ __forceinline__ void ldsm4(uint32_t* r, uint32_t a) {
    asm volatile("ldmatrix.sync.aligned.m8n8.x4.shared.b16 {%0,%1,%2,%3}, [%4];"
                 : "=r"(r[0]), "=r"(r[1]), "=r"(r[2]), "=r"(r[3]) : "r"(a));
}
__device__ __forceinline__ void ldsm4t(uint32_t* r, uint32_t a) {
    asm volatile("ldmatrix.sync.aligned.m8n8.x4.trans.shared.b16 {%0,%1,%2,%3}, [%4];"
                 : "=r"(r[0]), "=r"(r[1]), "=r"(r[2]), "=r"(r[3]) : "r"(a));
}
__device__ __forceinline__ void mma16816(float* d, const uint32_t* a, const uint32_t* b) {
    asm volatile(
        "mma.sync.aligned.m16n8k16.row.col.f32.bf16.bf16.f32 "
        "{%0,%1,%2,%3}, {%4,%5,%6,%7}, {%8,%9}, {%0,%1,%2,%3};"
        : "+f"(d[0]), "+f"(d[1]), "+f"(d[2]), "+f"(d[3])
        : "r"(a[0]), "r"(a[1]), "r"(a[2]), "r"(a[3]), "r"(b[0]), "r"(b[1]));
}
__device__ __forceinline__ uint32_t pack_hi(float a, float b) {
    __nv_bfloat162 p = __floats2bfloat162_rn(a, b);
    return *reinterpret_cast<uint32_t*>(&p);
}
__device__ __forceinline__ uint32_t pack_lo(float a, float b, uint32_t hi) {
    __nv_bfloat162 h = *reinterpret_cast<__nv_bfloat162*>(&hi);
    __nv_bfloat162 p = __floats2bfloat162_rn(a - __bfloat162float(h.x),
                                             b - __bfloat162float(h.y));
    return *reinterpret_cast<uint32_t*>(&p);
}

// ===========================================================================
// Kernel A (v3): hyper GEMM + fused BN. Same pipeline as proven R5 version
// but N=128 per CTA, 256 threads, 85KB smem -> 2 CTAs/SM, grid 1152.
// smem: A_HI@0 16896 | A_LO@16896 | F32@33792 2x16896 | BH@67584 | BL@76288
// ===========================================================================
#define HP_PITCH 528
#define HP_F32P  528
#define HP_BP    272
#define HP_RAHI  0
#define HP_RALO  16896
#define HP_RF32  33792
#define HP_F32B  16896
#define HP_RBH   67584
#define HP_RBL   76288
#define HP_SMEM  84992

__global__ __launch_bounds__(256, 2) void hyper_mma_kernel(
    const float* __restrict__ z, const float* __restrict__ dw,
    const float* __restrict__ db, const float* __restrict__ gamma,
    const float* __restrict__ beta)
{
    extern __shared__ char hs[];
    const uint32_t sb = smem_u32(hs);
    const int tid = threadIdx.x, wid = tid >> 5, lane = tid & 31;
    const int n0 = blockIdx.x * 128;
    const int wn0 = wid * 16;

    auto issue = [&](int s) {
#pragma unroll
        for (int i = 0; i < 4; i++) {
            int chunk = i * 256 + tid;
            int k = chunk >> 5, seg = chunk & 31;
            cp16(sb + HP_RF32 + (s & 1) * HP_F32B + k * HP_F32P + seg * 16,
                 dw + (size_t)(s * 32 + k) * NB + n0 + seg * 4);
        }
        CP_COMMIT();
    };
    issue(0);
    issue(1);

    // A (z) -> split bf16 smem [m=32][k=256]
    {
        const int m = tid >> 3, k0 = (tid & 7) * 32;
        const float4* zsrc = reinterpret_cast<const float4*>(z + m * ZD + k0);
        char* rowh = hs + HP_RAHI + m * HP_PITCH + k0 * 2;
        char* rowl = hs + HP_RALO + m * HP_PITCH + k0 * 2;
#pragma unroll
        for (int j = 0; j < 8; j++) {
            float4 v = zsrc[j];
            uint32_t h01 = pack_hi(v.x, v.y), h23 = pack_hi(v.z, v.w);
            uint32_t l01 = pack_lo(v.x, v.y, h01), l23 = pack_lo(v.z, v.w, h23);
            *reinterpret_cast<uint2*>(rowh + j * 8) = make_uint2(h01, h23);
            *reinterpret_cast<uint2*>(rowl + j * 8) = make_uint2(l01, l23);
        }
    }

    float d[2][2][4];
#pragma unroll
    for (int mt = 0; mt < 2; mt++)
#pragma unroll
        for (int nt = 0; nt < 2; nt++)
#pragma unroll
            for (int e = 0; e < 4; e++) d[mt][nt][e] = 0.0f;

    const uint32_t aoff = (uint32_t)((lane & 15) * HP_PITCH + (lane >> 4) * 16);
    const uint32_t boff = (uint32_t)((((lane >> 3) & 1) * 8 + (lane & 7)) * HP_BP
                                     + (wn0 + (lane >> 4) * 8) * 2);

    for (int s = 0; s < 8; s++) {
        if (s < 6) asm volatile("cp.async.wait_group 1;" ::: "memory");
        else       asm volatile("cp.async.wait_group 0;" ::: "memory");
        __syncthreads();

        // convert fp32 chunk [32k x 128n] -> BH/BL [k][n] bf16
        {
            const int k = tid >> 3;
            const float* frow = reinterpret_cast<const float*>(
                hs + HP_RF32 + (s & 1) * HP_F32B + k * HP_F32P);
            char* bh = hs + HP_RBH + k * HP_BP;
            char* bl = hs + HP_RBL + k * HP_BP;
            const int nb = (tid & 7) * 16;
#pragma unroll
            for (int j = 0; j < 4; j++) {
                int n4 = nb + j * 4;
                float4 v = *reinterpret_cast<const float4*>(frow + n4);
                uint32_t h01 = pack_hi(v.x, v.y), h23 = pack_hi(v.z, v.w);
                uint32_t l01 = pack_lo(v.x, v.y, h01), l23 = pack_lo(v.z, v.w, h23);
                *reinterpret_cast<uint2*>(bh + n4 * 2) = make_uint2(h01, h23);
                *reinterpret_cast<uint2*>(bl + n4 * 2) = make_uint2(l01, l23);
            }
        }
        __syncthreads();
        if (s + 2 < 8) issue(s + 2);

#pragma unroll
        for (int kk = 0; kk < 2; kk++) {
            uint32_t ah[2][4], al[2][4], bh[4], bl[4];
            const uint32_t akoff = (uint32_t)(s * 64 + kk * 32);
#pragma unroll
            for (int mt = 0; mt < 2; mt++) {
                ldsm4(ah[mt], sb + HP_RAHI + mt * 16 * HP_PITCH + akoff + aoff);
                ldsm4(al[mt], sb + HP_RALO + mt * 16 * HP_PITCH + akoff + aoff);
            }
            ldsm4t(bh, sb + HP_RBH + kk * 16 * HP_BP + boff);
            ldsm4t(bl, sb + HP_RBL + kk * 16 * HP_BP + boff);
#pragma unroll
            for (int mt = 0; mt < 2; mt++)
#pragma unroll
                for (int nt = 0; nt < 2; nt++) {
                    mma16816(d[mt][nt], ah[mt], &bh[nt * 2]);
                    mma16816(d[mt][nt], ah[mt], &bl[nt * 2]);
                    mma16816(d[mt][nt], al[mt], &bh[nt * 2]);
                }
        }
    }

    // ---- epilogue: relu + BN over 32 batch rows (warp-local) ----
    const int jc = n0 + wn0 + 2 * (lane & 3);
    float2 db2[2], g2[2], bt2[2];
#pragma unroll
    for (int nt = 0; nt < 2; nt++) {
        db2[nt] = *reinterpret_cast<const float2*>(db + jc + nt * 8);
        g2[nt]  = *reinterpret_cast<const float2*>(gamma + jc + nt * 8);
        bt2[nt] = *reinterpret_cast<const float2*>(beta + jc + nt * 8);
    }
#pragma unroll
    for (int mt = 0; mt < 2; mt++)
#pragma unroll
        for (int nt = 0; nt < 2; nt++) {
            d[mt][nt][0] = fmaxf(d[mt][nt][0] + db2[nt].x, 0.0f);
            d[mt][nt][1] = fmaxf(d[mt][nt][1] + db2[nt].y, 0.0f);
            d[mt][nt][2] = fmaxf(d[mt][nt][2] + db2[nt].x, 0.0f);
            d[mt][nt][3] = fmaxf(d[mt][nt][3] + db2[nt].y, 0.0f);
        }

    float sm[2][2], sq[2][2];
#pragma unroll
    for (int nt = 0; nt < 2; nt++)
#pragma unroll
        for (int c = 0; c < 2; c++) {
            float s1 = d[0][nt][c] + d[0][nt][c + 2] + d[1][nt][c] + d[1][nt][c + 2];
            float q1 = d[0][nt][c] * d[0][nt][c] + d[0][nt][c + 2] * d[0][nt][c + 2]
                     + d[1][nt][c] * d[1][nt][c] + d[1][nt][c + 2] * d[1][nt][c + 2];
#pragma unroll
            for (int o = 4; o < 32; o <<= 1) {
                s1 += __shfl_xor_sync(0xffffffffu, s1, o);
                q1 += __shfl_xor_sync(0xffffffffu, q1, o);
            }
            sm[nt][c] = s1 * (1.0f / 32.0f);
            float var = fmaxf(q1 * (1.0f / 32.0f) - sm[nt][c] * sm[nt][c], 0.0f);
            float gm = (c == 0) ? ((nt == 0) ? g2[0].x : g2[1].x)
                                : ((nt == 0) ? g2[0].y : g2[1].y);
            sq[nt][c] = gm / (sqrtf(var) + 1e-6f);
        }

    const int g = lane >> 2;
#pragma unroll
    for (int mt = 0; mt < 2; mt++)
#pragma unroll
        for (int nt = 0; nt < 2; nt++) {
            const int j = jc + nt * 8;
            float2 o0 = make_float2((d[mt][nt][0] - sm[nt][0]) * sq[nt][0] + bt2[nt].x,
                                    (d[mt][nt][1] - sm[nt][1]) * sq[nt][1] + bt2[nt].y);
            float2 o1 = make_float2((d[mt][nt][2] - sm[nt][0]) * sq[nt][0] + bt2[nt].x,
                                    (d[mt][nt][3] - sm[nt][1]) * sq[nt][1] + bt2[nt].y);
            *reinterpret_cast<float2*>(g_Wk + (size_t)(mt * 16 + g) * NB + j) = o0;
            *reinterpret_cast<float2*>(g_Wk + (size_t)(mt * 16 + g + 8) * NB + j) = o1;
        }
}

// ===========================================================================
// Kernel W: transpose + bf16-split W: (b,s,f,uv) fp32 -> (b,uv,f,s) hi/lo
// ===========================================================================
__global__ __launch_bounds__(256) void wtrans_kernel()
{
    __shared__ float sWk[9224];
    const int b = blockIdx.y, sblk = blockIdx.x, tid = threadIdx.x;
    const float* src = g_Wk + (size_t)b * NB + (size_t)sblk * 9216;
    for (int i = tid; i < 9216; i += 256) {
        int sl = i / 1152;
        sWk[i + sl] = src[i];
    }
    __syncthreads();
    for (int t = tid; t < 9216; t += 256) {
        int uv = t >> 10, f = (t >> 3) & 127, sl = t & 7;
        float v = sWk[sl * 1153 + f * 9 + uv];
        __nv_bfloat16 h = __float2bfloat16(v);
        __nv_bfloat16 l = __float2bfloat16(v - __bfloat162float(h));
        size_t o = (((size_t)(b * 9 + uv) * 128) + f) * 128 + sblk * 8 + sl;
        g_W2hi[o] = h;
        g_W2lo[o] = l;
    }
}

// ===========================================================================
// Kernel X: x -> padded channel-last split-bf16 (b, row 34, col 36, s 128)
// ===========================================================================
__global__ __launch_bounds__(256) void xprep_kernel(const float* __restrict__ x)
{
    __shared__ float sX[128 * 33];
    const int b = blockIdx.y, p = blockIdx.x, tid = threadIdx.x;
    for (int i = tid; i < 4096; i += 256) {
        int s = i >> 5, q = i & 31;
        sX[s * 33 + q] = x[(((size_t)(b * 128 + s)) * 32 + p) * 32 + q];
    }
    __syncthreads();
    for (int i = tid; i < 4096; i += 256) {
        int s = i & 127, q = i >> 7;
        float v = sX[s * 33 + q];
        __nv_bfloat16 h = __float2bfloat16(v);
        __nv_bfloat16 l = __float2bfloat16(v - __bfloat162float(h));
        size_t o = (((size_t)b * 34 + (p + 1)) * 36 + (q + 1)) * 128 + s;
        g_xhi[o] = h;
        g_xlo[o] = l;
    }
}

// ===========================================================================
// Kernel C (v4): conv GEMM, resident x-slice + 3-stage A pipeline, one
// __syncthreads per stage (extra sync + drain only at s-chunk boundary,
// which also makes the xslice(1) overwrite race-free).
// smem: XS @0 (97920) | A bufs @97920: 3 x 36864 -> 208512 B
// ===========================================================================
#define XSP    272
#define XSSZ   97920
#define APITCH 144
#define ABUF   36864
#define CSMEM  208512

__global__ __launch_bounds__(512, 1) void conv_mma_kernel(
    const float* __restrict__ xin,
    const float* __restrict__ bias,
    float* __restrict__ out)
{
    extern __shared__ char smem[];
    const uint32_t sb = smem_u32(smem);
    const int tid = threadIdx.x, wid = tid >> 5, lane = tid & 31;
    const int b = blockIdx.y, pb = blockIdx.x;   // pixel rows pb*8..pb*8+7
    const int f0 = (wid >> 2) * 32;
    const int px0 = (wid & 3) * 64;

    float d[2][8][4];
#pragma unroll
    for (int i = 0; i < 2; i++)
#pragma unroll
        for (int j = 0; j < 8; j++)
#pragma unroll
            for (int e = 0; e < 4; e++) d[i][j][e] = 0.0f;

    const uint32_t aoff = (uint32_t)((lane & 15) * APITCH + (lane >> 4) * 16);
    const uint32_t boffX = (uint32_t)(((lane & 7) + ((lane >> 4) << 3)) * XSP
                                      + ((lane >> 3) & 1) * 16);
    uint32_t bb[4];
#pragma unroll
    for (int p = 0; p < 4; p++) {
        int px = px0 + p * 16;
        bb[p] = (uint32_t)(((px >> 5) * 36 + (px & 31)) * XSP) + boffX;
    }

    auto load_xslice = [&](int sc) {
        for (int i = tid; i < 5760; i += 512) {
            int r = i / 576, rem = i % 576;
            int c = rem >> 4, h = (rem >> 3) & 1, seg = rem & 7;
            const __nv_bfloat16* src =
                (h ? g_xlo : g_xhi) +
                (((size_t)(b * 34 + pb * 8 + r)) * 36 + c) * 128 + sc * 64 + seg * 8;
            cp16(sb + (uint32_t)((r * 36 + c) * XSP + h * 128 + seg * 16), src);
        }
        CP_COMMIT();
    };

    auto issueA = [&](int ast) {
        const int uv = ast % 9, sc = ast / 9;
        const uint32_t base = sb + XSSZ + (uint32_t)(ast % 3) * ABUF;
#pragma unroll
        for (int i = 0; i < 4; i++) {
            int c2 = i * 512 + tid;
            int half = c2 >> 10, rem = c2 & 1023, row = rem >> 3, seg = rem & 7;
            const __nv_bfloat16* src =
                (half ? g_W2lo : g_W2hi) +
                (((size_t)(b * 9 + uv) * 128 + row) * 128 + sc * 64 + seg * 8);
            cp16(base + half * 18432 + row * APITCH + seg * 16, src);
        }
        CP_COMMIT();
    };

    load_xslice(0);
    issueA(0);
    issueA(1);

    for (int ast = 0; ast < 18; ast++) {
        if (ast == 9 || ast == 17) asm volatile("cp.async.wait_group 0;" ::: "memory");
        else                       asm volatile("cp.async.wait_group 1;" ::: "memory");
        __syncthreads();
        if (ast + 2 < 18) issueA(ast + 2);

        const int uv = ast % 9;
        const int u = uv / 3, v = uv - 3 * u;
        const uint32_t uvoff = (uint32_t)((u * 36 + v) * XSP);
        const uint32_t baseA = sb + XSSZ + (uint32_t)(ast % 3) * ABUF;
        const uint32_t baseAh = baseA, baseAl = baseA + 18432;

#pragma unroll
        for (int kk = 0; kk < 4; kk++) {
            const uint32_t ko = (uint32_t)kk * 32;
            uint32_t ah[2][4], al[2][4], bf[4][4];
#pragma unroll
            for (int i = 0; i < 2; i++) {
                ldsm4(ah[i], baseAh + (f0 + i * 16) * APITCH + ko + aoff);
                ldsm4(al[i], baseAl + (f0 + i * 16) * APITCH + ko + aoff);
            }
#pragma unroll
            for (int p = 0; p < 4; p++)
                ldsm4(bf[p], sb + bb[p] + uvoff + ko);          // x hi
#pragma unroll
            for (int i = 0; i < 2; i++)
#pragma unroll
                for (int t = 0; t < 8; t++)
                    mma16816(d[i][t], ah[i], &bf[t >> 1][(t & 1) * 2]);
#pragma unroll
            for (int i = 0; i < 2; i++)
#pragma unroll
                for (int t = 0; t < 8; t++)
                    mma16816(d[i][t], al[i], &bf[t >> 1][(t & 1) * 2]);
#pragma unroll
            for (int p = 0; p < 4; p++)
                ldsm4(bf[p], sb + bb[p] + uvoff + ko + 128);    // x lo
#pragma unroll
            for (int i = 0; i < 2; i++)
#pragma unroll
                for (int t = 0; t < 8; t++)
                    mma16816(d[i][t], ah[i], &bf[t >> 1][(t & 1) * 2]);
        }

        if (ast == 8) {            // chunk boundary: all readers of slice 0 done
            __syncthreads();
            load_xslice(1);
        }
    }

    // ---- epilogue: + residual + bias ----
    const int g = lane >> 2, tc = lane & 3;
#pragma unroll
    for (int i = 0; i < 2; i++) {
        const int fr0 = f0 + i * 16 + g;
        const float bv0 = __ldg(&bias[fr0]);
        const float bv1 = __ldg(&bias[fr0 + 8]);
#pragma unroll
        for (int j = 0; j < 8; j++) {
            const int pix = pb * 256 + px0 + j * 8 + tc * 2;
            {
                size_t o = ((size_t)(b * 128 + fr0)) * 1024 + pix;
                float2 xr = *reinterpret_cast<const float2*>(xin + o);
                float2 w = make_float2(d[i][j][0] + xr.x + bv0,
                                       d[i][j][1] + xr.y + bv0);
                *reinterpret_cast<float2*>(out + o) = w;
            }
            {
                size_t o = ((size_t)(b * 128 + fr0 + 8)) * 1024 + pix;
                float2 xr = *reinterpret_cast<const float2*>(xin + o);
                float2 w = make_float2(d[i][j][2] + xr.x + bv1,
                                       d[i][j][3] + xr.y + bv1);
                *reinterpret_cast<float2*>(out + o) = w;
            }
        }
    }
}

// ===========================================================================
extern "C" void kernel_launch(void* const* d_in, const int* in_sizes, int n_in,
                              void* d_out, int out_size)
{
    (void)in_sizes; (void)n_in; (void)out_size;
    const float* x     = (const float*)d_in[0];
    const float* z     = (const float*)d_in[1];
    const float* dw    = (const float*)d_in[2];
    const float* db    = (const float*)d_in[3];
    const float* gamma = (const float*)d_in[4];
    const float* beta  = (const float*)d_in[5];
    const float* bconv = (const float*)d_in[6];
    float* out = (float*)d_out;

    cudaFuncSetAttribute(hyper_mma_kernel,
                         cudaFuncAttributeMaxDynamicSharedMemorySize, HP_SMEM);
    cudaFuncSetAttribute(conv_mma_kernel,
                         cudaFuncAttributeMaxDynamicSharedMemorySize, CSMEM);

    hyper_mma_kernel<<<NB / 128, 256, HP_SMEM>>>(z, dw, db, gamma, beta);
    xprep_kernel<<<dim3(32, BATCH), 256>>>(x);
    wtrans_kernel<<<dim3(16, BATCH), 256>>>();
    conv_mma_kernel<<<dim3(4, BATCH), 512, CSMEM>>>(x, bconv, out);
}

// round 9
// speedup vs baseline: 1.1433x; 1.1433x over previous
#include <cuda_runtime.h>
#include <cuda_bf16.h>
#include <cstdint>

#define CIN   128
#define COUT  128
#define KHW   9
#define NB    (CIN*COUT*KHW)   // 147456
#define ZD    256
#define BATCH 32
#define HW    32
#define HW2   (HW*HW)

// ---------------- scratch (device globals; no allocs allowed) ----------------
__device__ __align__(1024) float          g_Wk[BATCH * NB];                 // fp32 (b,s,f,uv)
__device__ __align__(1024) __nv_bfloat16  g_W2hi[BATCH * 9 * 128 * 128];    // (b,uv,f,s)
__device__ __align__(1024) __nv_bfloat16  g_W2lo[BATCH * 9 * 128 * 128];
__device__ __align__(1024) __nv_bfloat16  g_xhi[BATCH * 34 * 36 * 128];     // (b,row,col,s) padded, pad stays 0
__device__ __align__(1024) __nv_bfloat16  g_xlo[BATCH * 34 * 36 * 128];

// ---------------- helpers ----------------
__device__ __forceinline__ uint32_t smem_u32(const void* p) {
    uint32_t a;
    asm("{ .reg .u64 t; cvta.to.shared.u64 t, %1; cvt.u32.u64 %0, t; }" : "=r"(a) : "l"(p));
    return a;
}
__device__ __forceinline__ void cp16(uint32_t dst, const void* src) {
    asm volatile("cp.async.cg.shared.global [%0], [%1], 16;" :: "r"(dst), "l"(src) : "memory");
}
#define CP_COMMIT() asm volatile("cp.async.commit_group;" ::: "memory")

__device__ __forceinline__ void ldsm4(uint32_t* r, uint32_t a) {
    asm volatile("ldmatrix.sync.aligned.m8n8.x4.shared.b16 {%0,%1,%2,%3}, [%4];"
                 : "=r"(r[0]), "=r"(r[1]), "=r"(r[2]), "=r"(r[3]) : "r"(a));
}
__device__ __forceinline__ void mma16816(float* d, const uint32_t* a, const uint32_t* b) {
    asm volatile(
        "mma.sync.aligned.m16n8k16.row.col.f32.bf16.bf16.f32 "
        "{%0,%1,%2,%3}, {%4,%5,%6,%7}, {%8,%9}, {%0,%1,%2,%3};"
        : "+f"(d[0]), "+f"(d[1]), "+f"(d[2]), "+f"(d[3])
        : "r"(a[0]), "r"(a[1]), "r"(a[2]), "r"(a[3]), "r"(b[0]), "r"(b[1]));
}
__device__ __forceinline__ void mma1688_tf32(float* d, const uint32_t* a, const uint32_t* b) {
    asm volatile(
        "mma.sync.aligned.m16n8k8.row.col.f32.tf32.tf32.f32 "
        "{%0,%1,%2,%3}, {%4,%5,%6,%7}, {%8,%9}, {%0,%1,%2,%3};"
        : "+f"(d[0]), "+f"(d[1]), "+f"(d[2]), "+f"(d[3])
        : "r"(a[0]), "r"(a[1]), "r"(a[2]), "r"(a[3]), "r"(b[0]), "r"(b[1]));
}
__device__ __forceinline__ uint32_t cvt_tf32(float f) {
    uint32_t r;
    asm("cvt.rna.tf32.f32 %0, %1;" : "=r"(r) : "f"(f));
    return r;
}
__device__ __forceinline__ uint32_t lds32(uint32_t a) {
    uint32_t r;
    asm volatile("ld.shared.b32 %0, [%1];" : "=r"(r) : "r"(a));
    return r;
}
__device__ __forceinline__ uint32_t pack_hi(float a, float b) {
    __nv_bfloat162 p = __floats2bfloat162_rn(a, b);
    return *reinterpret_cast<uint32_t*>(&p);
}

// ===========================================================================
// Kernel A (tf32): hyper GEMM + fused BN, no bulk conversion.
//   M=32, K=256, N=256 per CTA (576 CTAs), 512 thr.
//   dw cp.async'd fp32 into 3-buffer ring; fragments via LDS.32 + cvt.rna.
// smem: A @0 32x268 fp32 (34304B) | B @34304: 3 x (32 x 264 fp32 = 33792B)
// ===========================================================================
#define H2_APW 268            // A pitch in floats
#define H2_BPW 264            // B pitch in floats
#define H2_RB  34304
#define H2_BBUF 33792
#define H2_SMEM 135680

__global__ __launch_bounds__(512, 1) void hyper_tf32_kernel(
    const float* __restrict__ z, const float* __restrict__ dw,
    const float* __restrict__ db, const float* __restrict__ gamma,
    const float* __restrict__ beta)
{
    extern __shared__ char hs[];
    const uint32_t sb = smem_u32(hs);
    const int tid = threadIdx.x, wid = tid >> 5, lane = tid & 31;
    const int n0 = blockIdx.x * 256;
    const int wn0 = wid * 16;
    const int g = lane >> 2, tig = lane & 3;

    auto issue = [&](int s) {
#pragma unroll
        for (int i = 0; i < 4; i++) {
            int chunk = i * 512 + tid;
            int k = chunk >> 6, seg = chunk & 63;
            cp16(sb + H2_RB + (uint32_t)(s % 3) * H2_BBUF + k * (H2_BPW * 4) + seg * 16,
                 dw + (size_t)(s * 32 + k) * NB + n0 + seg * 4);
        }
        CP_COMMIT();
    };
    issue(0);
    issue(1);

    // A (z) -> tf32 (rna) smem [m=32][k=256], pitch 268 floats
    {
        const int m = tid >> 4, k0 = (tid & 15) * 16;
        const float4* zsrc = reinterpret_cast<const float4*>(z + m * ZD + k0);
        uint32_t* arow = reinterpret_cast<uint32_t*>(hs) + m * H2_APW + k0;
#pragma unroll
        for (int j = 0; j < 4; j++) {
            float4 v = zsrc[j];
            arow[j * 4 + 0] = cvt_tf32(v.x);
            arow[j * 4 + 1] = cvt_tf32(v.y);
            arow[j * 4 + 2] = cvt_tf32(v.z);
            arow[j * 4 + 3] = cvt_tf32(v.w);
        }
    }

    float d[2][2][4];
#pragma unroll
    for (int mt = 0; mt < 2; mt++)
#pragma unroll
        for (int nt = 0; nt < 2; nt++)
#pragma unroll
            for (int e = 0; e < 4; e++) d[mt][nt][e] = 0.0f;

    // A fragment base (bytes): row g, col tig
    const uint32_t abase = sb + (uint32_t)(g * H2_APW + tig) * 4;

    for (int s = 0; s < 8; s++) {
        if (s < 6) asm volatile("cp.async.wait_group 1;" ::: "memory");
        else       asm volatile("cp.async.wait_group 0;" ::: "memory");
        __syncthreads();
        if (s + 2 < 8) issue(s + 2);

        const uint32_t bbuf = sb + H2_RB + (uint32_t)(s % 3) * H2_BBUF;
#pragma unroll
        for (int kk = 0; kk < 4; kk++) {
            const uint32_t acol = (uint32_t)(s * 32 + kk * 8) * 4;
            uint32_t a[2][4], bfr[2][2];
#pragma unroll
            for (int mt = 0; mt < 2; mt++) {
                const uint32_t ab = abase + (uint32_t)(mt * 16 * H2_APW) * 4 + acol;
                a[mt][0] = lds32(ab);
                a[mt][1] = lds32(ab + (uint32_t)(8 * H2_APW) * 4);
                a[mt][2] = lds32(ab + 16);
                a[mt][3] = lds32(ab + (uint32_t)(8 * H2_APW) * 4 + 16);
            }
#pragma unroll
            for (int nt = 0; nt < 2; nt++) {
                const uint32_t bb = bbuf + (uint32_t)((kk * 8 + tig) * H2_BPW
                                                      + wn0 + nt * 8 + g) * 4;
                bfr[nt][0] = cvt_tf32(__uint_as_float(lds32(bb)));
                bfr[nt][1] = cvt_tf32(__uint_as_float(lds32(bb + (uint32_t)(4 * H2_BPW) * 4)));
            }
#pragma unroll
            for (int mt = 0; mt < 2; mt++)
#pragma unroll
                for (int nt = 0; nt < 2; nt++)
                    mma1688_tf32(d[mt][nt], a[mt], bfr[nt]);
        }
    }

    // ---- epilogue: relu + BN over 32 batch rows (warp-local) ----
    const int jc = n0 + wn0 + 2 * (lane & 3);
    float2 db2[2], g2[2], bt2[2];
#pragma unroll
    for (int nt = 0; nt < 2; nt++) {
        db2[nt] = *reinterpret_cast<const float2*>(db + jc + nt * 8);
        g2[nt]  = *reinterpret_cast<const float2*>(gamma + jc + nt * 8);
        bt2[nt] = *reinterpret_cast<const float2*>(beta + jc + nt * 8);
    }
#pragma unroll
    for (int mt = 0; mt < 2; mt++)
#pragma unroll
        for (int nt = 0; nt < 2; nt++) {
            d[mt][nt][0] = fmaxf(d[mt][nt][0] + db2[nt].x, 0.0f);
            d[mt][nt][1] = fmaxf(d[mt][nt][1] + db2[nt].y, 0.0f);
            d[mt][nt][2] = fmaxf(d[mt][nt][2] + db2[nt].x, 0.0f);
            d[mt][nt][3] = fmaxf(d[mt][nt][3] + db2[nt].y, 0.0f);
        }

    float sm[2][2], sq[2][2];
#pragma unroll
    for (int nt = 0; nt < 2; nt++)
#pragma unroll
        for (int c = 0; c < 2; c++) {
            float s1 = d[0][nt][c] + d[0][nt][c + 2] + d[1][nt][c] + d[1][nt][c + 2];
            float q1 = d[0][nt][c] * d[0][nt][c] + d[0][nt][c + 2] * d[0][nt][c + 2]
                     + d[1][nt][c] * d[1][nt][c] + d[1][nt][c + 2] * d[1][nt][c + 2];
#pragma unroll
            for (int o = 4; o < 32; o <<= 1) {
                s1 += __shfl_xor_sync(0xffffffffu, s1, o);
                q1 += __shfl_xor_sync(0xffffffffu, q1, o);
            }
            sm[nt][c] = s1 * (1.0f / 32.0f);
            float var = fmaxf(q1 * (1.0f / 32.0f) - sm[nt][c] * sm[nt][c], 0.0f);
            float gm = (c == 0) ? ((nt == 0) ? g2[0].x : g2[1].x)
                                : ((nt == 0) ? g2[0].y : g2[1].y);
            sq[nt][c] = gm / (sqrtf(var) + 1e-6f);
        }

#pragma unroll
    for (int mt = 0; mt < 2; mt++)
#pragma unroll
        for (int nt = 0; nt < 2; nt++) {
            const int j = jc + nt * 8;
            float2 o0 = make_float2((d[mt][nt][0] - sm[nt][0]) * sq[nt][0] + bt2[nt].x,
                                    (d[mt][nt][1] - sm[nt][1]) * sq[nt][1] + bt2[nt].y);
            float2 o1 = make_float2((d[mt][nt][2] - sm[nt][0]) * sq[nt][0] + bt2[nt].x,
                                    (d[mt][nt][3] - sm[nt][1]) * sq[nt][1] + bt2[nt].y);
            *reinterpret_cast<float2*>(g_Wk + (size_t)(mt * 16 + g) * NB + j) = o0;
            *reinterpret_cast<float2*>(g_Wk + (size_t)(mt * 16 + g + 8) * NB + j) = o1;
        }
}

// ===========================================================================
// Kernel W: transpose + bf16-split W: (b,s,f,uv) fp32 -> (b,uv,f,s) hi/lo
// ===========================================================================
__global__ __launch_bounds__(256) void wtrans_kernel()
{
    __shared__ float sWk[9224];
    const int b = blockIdx.y, sblk = blockIdx.x, tid = threadIdx.x;
    const float* src = g_Wk + (size_t)b * NB + (size_t)sblk * 9216;
    for (int i = tid; i < 9216; i += 256) {
        int sl = i / 1152;
        sWk[i + sl] = src[i];
    }
    __syncthreads();
    for (int t = tid; t < 9216; t += 256) {
        int uv = t >> 10, f = (t >> 3) & 127, sl = t & 7;
        float v = sWk[sl * 1153 + f * 9 + uv];
        __nv_bfloat16 h = __float2bfloat16(v);
        __nv_bfloat16 l = __float2bfloat16(v - __bfloat162float(h));
        size_t o = (((size_t)(b * 9 + uv) * 128) + f) * 128 + sblk * 8 + sl;
        g_W2hi[o] = h;
        g_W2lo[o] = l;
    }
}

// ===========================================================================
// Kernel X: x -> padded channel-last split-bf16 (b, row 34, col 36, s 128)
// ===========================================================================
__global__ __launch_bounds__(256) void xprep_kernel(const float* __restrict__ x)
{
    __shared__ float sX[128 * 33];
    const int b = blockIdx.y, p = blockIdx.x, tid = threadIdx.x;
    for (int i = tid; i < 4096; i += 256) {
        int s = i >> 5, q = i & 31;
        sX[s * 33 + q] = x[(((size_t)(b * 128 + s)) * 32 + p) * 32 + q];
    }
    __syncthreads();
    for (int i = tid; i < 4096; i += 256) {
        int s = i & 127, q = i >> 7;
        float v = sX[s * 33 + q];
        __nv_bfloat16 h = __float2bfloat16(v);
        __nv_bfloat16 l = __float2bfloat16(v - __bfloat162float(h));
        size_t o = (((size_t)b * 34 + (p + 1)) * 36 + (q + 1)) * 128 + s;
        g_xhi[o] = h;
        g_xlo[o] = l;
    }
}

// ===========================================================================
// Kernel C (v4): conv GEMM, resident x-slice + 3-stage A pipeline (proven R8).
// smem: XS @0 (97920) | A bufs @97920: 3 x 36864 -> 208512 B
// ===========================================================================
#define XSP    272
#define XSSZ   97920
#define APITCH 144
#define ABUF   36864
#define CSMEM  208512

__global__ __launch_bounds__(512, 1) void conv_mma_kernel(
    const float* __restrict__ xin,
    const float* __restrict__ bias,
    float* __restrict__ out)
{
    extern __shared__ char smem[];
    const uint32_t sb = smem_u32(smem);
    const int tid = threadIdx.x, wid = tid >> 5, lane = tid & 31;
    const int b = blockIdx.y, pb = blockIdx.x;
    const int f0 = (wid >> 2) * 32;
    const int px0 = (wid & 3) * 64;

    float d[2][8][4];
#pragma unroll
    for (int i = 0; i < 2; i++)
#pragma unroll
        for (int j = 0; j < 8; j++)
#pragma unroll
            for (int e = 0; e < 4; e++) d[i][j][e] = 0.0f;

    const uint32_t aoff = (uint32_t)((lane & 15) * APITCH + (lane >> 4) * 16);
    const uint32_t boffX = (uint32_t)(((lane & 7) + ((lane >> 4) << 3)) * XSP
                                      + ((lane >> 3) & 1) * 16);
    uint32_t bb[4];
#pragma unroll
    for (int p = 0; p < 4; p++) {
        int px = px0 + p * 16;
        bb[p] = (uint32_t)(((px >> 5) * 36 + (px & 31)) * XSP) + boffX;
    }

    auto load_xslice = [&](int sc) {
        for (int i = tid; i < 5760; i += 512) {
            int r = i / 576, rem = i % 576;
            int c = rem >> 4, h = (rem >> 3) & 1, seg = rem & 7;
            const __nv_bfloat16* src =
                (h ? g_xlo : g_xhi) +
                (((size_t)(b * 34 + pb * 8 + r)) * 36 + c) * 128 + sc * 64 + seg * 8;
            cp16(sb + (uint32_t)((r * 36 + c) * XSP + h * 128 + seg * 16), src);
        }
        CP_COMMIT();
    };

    auto issueA = [&](int ast) {
        const int uv = ast % 9, sc = ast / 9;
        const uint32_t base = sb + XSSZ + (uint32_t)(ast % 3) * ABUF;
#pragma unroll
        for (int i = 0; i < 4; i++) {
            int c2 = i * 512 + tid;
            int half = c2 >> 10, rem = c2 & 1023, row = rem >> 3, seg = rem & 7;
            const __nv_bfloat16* src =
                (half ? g_W2lo : g_W2hi) +
                (((size_t)(b * 9 + uv) * 128 + row) * 128 + sc * 64 + seg * 8);
            cp16(base + half * 18432 + row * APITCH + seg * 16, src);
        }
        CP_COMMIT();
    };

    load_xslice(0);
    issueA(0);
    issueA(1);

    for (int ast = 0; ast < 18; ast++) {
        if (ast == 9 || ast == 17) asm volatile("cp.async.wait_group 0;" ::: "memory");
        else                       asm volatile("cp.async.wait_group 1;" ::: "memory");
        __syncthreads();
        if (ast + 2 < 18) issueA(ast + 2);

        const int uv = ast % 9;
        const int u = uv / 3, v = uv - 3 * u;
        const uint32_t uvoff = (uint32_t)((u * 36 + v) * XSP);
        const uint32_t baseA = sb + XSSZ + (uint32_t)(ast % 3) * ABUF;
        const uint32_t baseAh = baseA, baseAl = baseA + 18432;

#pragma unroll
        for (int kk = 0; kk < 4; kk++) {
            const uint32_t ko = (uint32_t)kk * 32;
            uint32_t ah[2][4], al[2][4], bf[4][4];
#pragma unroll
            for (int i = 0; i < 2; i++) {
                ldsm4(ah[i], baseAh + (f0 + i * 16) * APITCH + ko + aoff);
                ldsm4(al[i], baseAl + (f0 + i * 16) * APITCH + ko + aoff);
            }
#pragma unroll
            for (int p = 0; p < 4; p++)
                ldsm4(bf[p], sb + bb[p] + uvoff + ko);          // x hi
#pragma unroll
            for (int i = 0; i < 2; i++)
#pragma unroll
                for (int t = 0; t < 8; t++)
                    mma16816(d[i][t], ah[i], &bf[t >> 1][(t & 1) * 2]);
#pragma unroll
            for (int i = 0; i < 2; i++)
#pragma unroll
                for (int t = 0; t < 8; t++)
                    mma16816(d[i][t], al[i], &bf[t >> 1][(t & 1) * 2]);
#pragma unroll
            for (int p = 0; p < 4; p++)
                ldsm4(bf[p], sb + bb[p] + uvoff + ko + 128);    // x lo
#pragma unroll
            for (int i = 0; i < 2; i++)
#pragma unroll
                for (int t = 0; t < 8; t++)
                    mma16816(d[i][t], ah[i], &bf[t >> 1][(t & 1) * 2]);
        }

        if (ast == 8) {
            __syncthreads();
            load_xslice(1);
        }
    }

    // ---- epilogue: + residual + bias ----
    const int g = lane >> 2, tc = lane & 3;
#pragma unroll
    for (int i = 0; i < 2; i++) {
        const int fr0 = f0 + i * 16 + g;
        const float bv0 = __ldg(&bias[fr0]);
        const float bv1 = __ldg(&bias[fr0 + 8]);
#pragma unroll
        for (int j = 0; j < 8; j++) {
            const int pix = pb * 256 + px0 + j * 8 + tc * 2;
            {
                size_t o = ((size_t)(b * 128 + fr0)) * 1024 + pix;
                float2 xr = *reinterpret_cast<const float2*>(xin + o);
                float2 w = make_float2(d[i][j][0] + xr.x + bv0,
                                       d[i][j][1] + xr.y + bv0);
                *reinterpret_cast<float2*>(out + o) = w;
            }
            {
                size_t o = ((size_t)(b * 128 + fr0 + 8)) * 1024 + pix;
                float2 xr = *reinterpret_cast<const float2*>(xin + o);
                float2 w = make_float2(d[i][j][2] + xr.x + bv1,
                                       d[i][j][3] + xr.y + bv1);
                *reinterpret_cast<float2*>(out + o) = w;
            }
        }
    }
}

// ===========================================================================
extern "C" void kernel_launch(void* const* d_in, const int* in_sizes, int n_in,
                              void* d_out, int out_size)
{
    (void)in_sizes; (void)n_in; (void)out_size;
    const float* x     = (const float*)d_in[0];
    const float* z     = (const float*)d_in[1];
    const float* dw    = (const float*)d_in[2];
    const float* db    = (const float*)d_in[3];
    const float* gamma = (const float*)d_in[4];
    const float* beta  = (const float*)d_in[5];
    const float* bconv = (const float*)d_in[6];
    float* out = (float*)d_out;

    cudaFuncSetAttribute(hyper_tf32_kernel,
                         cudaFuncAttributeMaxDynamicSharedMemorySize, H2_SMEM);
    cudaFuncSetAttribute(conv_mma_kernel,
                         cudaFuncAttributeMaxDynamicSharedMemorySize, CSMEM);

    hyper_tf32_kernel<<<NB / 256, 512, H2_SMEM>>>(z, dw, db, gamma, beta);
    xprep_kernel<<<dim3(32, BATCH), 256>>>(x);
    wtrans_kernel<<<dim3(16, BATCH), 256>>>();
    conv_mma_kernel<<<dim3(4, BATCH), 512, CSMEM>>>(x, bconv, out);
}

// round 10
// speedup vs baseline: 1.3444x; 1.1759x over previous
#include <cuda_runtime.h>
#include <cuda_bf16.h>
#include <cstdint>

#define CIN   128
#define COUT  128
#define KHW   9
#define NB    (CIN*COUT*KHW)   // 147456
#define ZD    256
#define BATCH 32
#define HW    32
#define HW2   (HW*HW)

// ---------------- scratch (device globals; no allocs allowed) ----------------
__device__ __align__(1024) float g_Wk[BATCH * NB];                 // fp32 (b,s,f,uv)
__device__ __align__(1024) float g_Wt[BATCH * 9 * 128 * 128];      // tf32-rounded (b,uv,f,s)
__device__ __align__(1024) float g_xt[BATCH * 34 * 36 * 128];      // tf32-rounded (b,row,col,s); pad stays 0

// ---------------- helpers ----------------
__device__ __forceinline__ uint32_t smem_u32(const void* p) {
    uint32_t a;
    asm("{ .reg .u64 t; cvta.to.shared.u64 t, %1; cvt.u32.u64 %0, t; }" : "=r"(a) : "l"(p));
    return a;
}
__device__ __forceinline__ void cp16(uint32_t dst, const void* src) {
    asm volatile("cp.async.cg.shared.global [%0], [%1], 16;" :: "r"(dst), "l"(src) : "memory");
}
#define CP_COMMIT() asm volatile("cp.async.commit_group;" ::: "memory")

__device__ __forceinline__ void mma1688_tf32(float* d, const uint32_t* a, const uint32_t* b) {
    asm volatile(
        "mma.sync.aligned.m16n8k8.row.col.f32.tf32.tf32.f32 "
        "{%0,%1,%2,%3}, {%4,%5,%6,%7}, {%8,%9}, {%0,%1,%2,%3};"
        : "+f"(d[0]), "+f"(d[1]), "+f"(d[2]), "+f"(d[3])
        : "r"(a[0]), "r"(a[1]), "r"(a[2]), "r"(a[3]), "r"(b[0]), "r"(b[1]));
}
__device__ __forceinline__ uint32_t cvt_tf32(float f) {
    uint32_t r;
    asm("cvt.rna.tf32.f32 %0, %1;" : "=r"(r) : "f"(f));
    return r;
}
__device__ __forceinline__ uint32_t lds32(uint32_t a) {
    uint32_t r;
    asm volatile("ld.shared.b32 %0, [%1];" : "=r"(r) : "r"(a));
    return r;
}

// ===========================================================================
// Kernel A (tf32, 4-buffer): hyper GEMM + fused BN.
//   M=32, K=256, N=256 per CTA (576 CTAs), 512 thr, prefetch depth 3.
// smem: A @0 32x268 fp32 (34304B) | B @34304: 4 x (32 x 264 fp32 = 33792B)
// ===========================================================================
#define H2_APW 268
#define H2_BPW 264
#define H2_RB  34304
#define H2_BBUF 33792
#define H2_SMEM 169472

__global__ __launch_bounds__(512, 1) void hyper_tf32_kernel(
    const float* __restrict__ z, const float* __restrict__ dw,
    const float* __restrict__ db, const float* __restrict__ gamma,
    const float* __restrict__ beta)
{
    extern __shared__ char hs[];
    const uint32_t sb = smem_u32(hs);
    const int tid = threadIdx.x, wid = tid >> 5, lane = tid & 31;
    const int n0 = blockIdx.x * 256;
    const int wn0 = wid * 16;
    const int g = lane >> 2, tig = lane & 3;

    auto issue = [&](int s) {
#pragma unroll
        for (int i = 0; i < 4; i++) {
            int chunk = i * 512 + tid;
            int k = chunk >> 6, seg = chunk & 63;
            cp16(sb + H2_RB + (uint32_t)(s & 3) * H2_BBUF + k * (H2_BPW * 4) + seg * 16,
                 dw + (size_t)(s * 32 + k) * NB + n0 + seg * 4);
        }
        CP_COMMIT();
    };
    issue(0);
    issue(1);
    issue(2);

    // A (z) -> tf32 (rna) smem [m=32][k=256]
    {
        const int m = tid >> 4, k0 = (tid & 15) * 16;
        const float4* zsrc = reinterpret_cast<const float4*>(z + m * ZD + k0);
        uint32_t* arow = reinterpret_cast<uint32_t*>(hs) + m * H2_APW + k0;
#pragma unroll
        for (int j = 0; j < 4; j++) {
            float4 v = zsrc[j];
            arow[j * 4 + 0] = cvt_tf32(v.x);
            arow[j * 4 + 1] = cvt_tf32(v.y);
            arow[j * 4 + 2] = cvt_tf32(v.z);
            arow[j * 4 + 3] = cvt_tf32(v.w);
        }
    }

    float d[2][2][4];
#pragma unroll
    for (int mt = 0; mt < 2; mt++)
#pragma unroll
        for (int nt = 0; nt < 2; nt++)
#pragma unroll
            for (int e = 0; e < 4; e++) d[mt][nt][e] = 0.0f;

    const uint32_t abase = sb + (uint32_t)(g * H2_APW + tig) * 4;

    for (int s = 0; s < 8; s++) {
        if (s < 5)      asm volatile("cp.async.wait_group 2;" ::: "memory");
        else if (s == 5) asm volatile("cp.async.wait_group 2;" ::: "memory");
        else if (s == 6) asm volatile("cp.async.wait_group 1;" ::: "memory");
        else             asm volatile("cp.async.wait_group 0;" ::: "memory");
        __syncthreads();
        if (s + 3 < 8) issue(s + 3);

        const uint32_t bbuf = sb + H2_RB + (uint32_t)(s & 3) * H2_BBUF;
#pragma unroll
        for (int kk = 0; kk < 4; kk++) {
            const uint32_t acol = (uint32_t)(s * 32 + kk * 8) * 4;
            uint32_t a[2][4], bfr[2][2];
#pragma unroll
            for (int mt = 0; mt < 2; mt++) {
                const uint32_t ab = abase + (uint32_t)(mt * 16 * H2_APW) * 4 + acol;
                a[mt][0] = lds32(ab);
                a[mt][1] = lds32(ab + (uint32_t)(8 * H2_APW) * 4);
                a[mt][2] = lds32(ab + 16);
                a[mt][3] = lds32(ab + (uint32_t)(8 * H2_APW) * 4 + 16);
            }
#pragma unroll
            for (int nt = 0; nt < 2; nt++) {
                const uint32_t bb = bbuf + (uint32_t)((kk * 8 + tig) * H2_BPW
                                                      + wn0 + nt * 8 + g) * 4;
                bfr[nt][0] = cvt_tf32(__uint_as_float(lds32(bb)));
                bfr[nt][1] = cvt_tf32(__uint_as_float(lds32(bb + (uint32_t)(4 * H2_BPW) * 4)));
            }
#pragma unroll
            for (int mt = 0; mt < 2; mt++)
#pragma unroll
                for (int nt = 0; nt < 2; nt++)
                    mma1688_tf32(d[mt][nt], a[mt], bfr[nt]);
        }
    }

    // ---- epilogue: relu + BN over 32 batch rows (warp-local) ----
    const int jc = n0 + wn0 + 2 * (lane & 3);
    float2 db2[2], g2[2], bt2[2];
#pragma unroll
    for (int nt = 0; nt < 2; nt++) {
        db2[nt] = *reinterpret_cast<const float2*>(db + jc + nt * 8);
        g2[nt]  = *reinterpret_cast<const float2*>(gamma + jc + nt * 8);
        bt2[nt] = *reinterpret_cast<const float2*>(beta + jc + nt * 8);
    }
#pragma unroll
    for (int mt = 0; mt < 2; mt++)
#pragma unroll
        for (int nt = 0; nt < 2; nt++) {
            d[mt][nt][0] = fmaxf(d[mt][nt][0] + db2[nt].x, 0.0f);
            d[mt][nt][1] = fmaxf(d[mt][nt][1] + db2[nt].y, 0.0f);
            d[mt][nt][2] = fmaxf(d[mt][nt][2] + db2[nt].x, 0.0f);
            d[mt][nt][3] = fmaxf(d[mt][nt][3] + db2[nt].y, 0.0f);
        }

    float sm[2][2], sq[2][2];
#pragma unroll
    for (int nt = 0; nt < 2; nt++)
#pragma unroll
        for (int c = 0; c < 2; c++) {
            float s1 = d[0][nt][c] + d[0][nt][c + 2] + d[1][nt][c] + d[1][nt][c + 2];
            float q1 = d[0][nt][c] * d[0][nt][c] + d[0][nt][c + 2] * d[0][nt][c + 2]
                     + d[1][nt][c] * d[1][nt][c] + d[1][nt][c + 2] * d[1][nt][c + 2];
#pragma unroll
            for (int o = 4; o < 32; o <<= 1) {
                s1 += __shfl_xor_sync(0xffffffffu, s1, o);
                q1 += __shfl_xor_sync(0xffffffffu, q1, o);
            }
            sm[nt][c] = s1 * (1.0f / 32.0f);
            float var = fmaxf(q1 * (1.0f / 32.0f) - sm[nt][c] * sm[nt][c], 0.0f);
            float gm = (c == 0) ? ((nt == 0) ? g2[0].x : g2[1].x)
                                : ((nt == 0) ? g2[0].y : g2[1].y);
            sq[nt][c] = gm / (sqrtf(var) + 1e-6f);
        }

#pragma unroll
    for (int mt = 0; mt < 2; mt++)
#pragma unroll
        for (int nt = 0; nt < 2; nt++) {
            const int j = jc + nt * 8;
            float2 o0 = make_float2((d[mt][nt][0] - sm[nt][0]) * sq[nt][0] + bt2[nt].x,
                                    (d[mt][nt][1] - sm[nt][1]) * sq[nt][1] + bt2[nt].y);
            float2 o1 = make_float2((d[mt][nt][2] - sm[nt][0]) * sq[nt][0] + bt2[nt].x,
                                    (d[mt][nt][3] - sm[nt][1]) * sq[nt][1] + bt2[nt].y);
            *reinterpret_cast<float2*>(g_Wk + (size_t)(mt * 16 + g) * NB + j) = o0;
            *reinterpret_cast<float2*>(g_Wk + (size_t)(mt * 16 + g + 8) * NB + j) = o1;
        }
}

// ===========================================================================
// Kernel W: transpose W (b,s,f,uv) fp32 -> (b,uv,f,s) tf32-rounded fp32
// ===========================================================================
__global__ __launch_bounds__(256) void wtrans_kernel()
{
    __shared__ float sWk[9224];
    const int b = blockIdx.y, sblk = blockIdx.x, tid = threadIdx.x;
    const float* src = g_Wk + (size_t)b * NB + (size_t)sblk * 9216;
    for (int i = tid; i < 9216; i += 256) {
        int sl = i / 1152;
        sWk[i + sl] = src[i];
    }
    __syncthreads();
    for (int t = tid; t < 9216; t += 256) {
        int uv = t >> 10, f = (t >> 3) & 127, sl = t & 7;
        float v = sWk[sl * 1153 + f * 9 + uv];
        size_t o = (((size_t)(b * 9 + uv) * 128) + f) * 128 + sblk * 8 + sl;
        g_Wt[o] = __uint_as_float(cvt_tf32(v));
    }
}

// ===========================================================================
// Kernel X: x -> padded channel-last tf32-rounded fp32 (b, row34, col36, s128)
// ===========================================================================
__global__ __launch_bounds__(256) void xprep_kernel(const float* __restrict__ x)
{
    __shared__ float sX[128 * 33];
    const int b = blockIdx.y, p = blockIdx.x, tid = threadIdx.x;
    for (int i = tid; i < 4096; i += 256) {
        int s = i >> 5, q = i & 31;
        sX[s * 33 + q] = x[(((size_t)(b * 128 + s)) * 32 + p) * 32 + q];
    }
    __syncthreads();
    for (int i = tid; i < 4096; i += 256) {
        int s = i & 127, q = i >> 7;
        float v = sX[s * 33 + q];
        size_t o = (((size_t)b * 34 + (p + 1)) * 36 + (q + 1)) * 128 + s;
        g_xt[o] = __uint_as_float(cvt_tf32(v));
    }
}

// ===========================================================================
// Kernel C (tf32): conv GEMM, resident fp32 x-slice + 3-stage A pipeline.
//   CTA = (pxblock 8 rows = N 256, b), 512 thr, warp tile 32f x 64px.
//   18 stages of (uv, 64s); k8 MMAs; operands pre-rounded to tf32 in preps.
// x-slice: [10 r][36 c][68 fl pitch] = 97920 B; A bufs: 3 x 128x68fl = 104448
// ===========================================================================
#define XSP    272          // 68 floats
#define XSSZ   97920
#define ABUF   34816
#define CSMEM  202368

__global__ __launch_bounds__(512, 1) void conv_mma_kernel(
    const float* __restrict__ xin,
    const float* __restrict__ bias,
    float* __restrict__ out)
{
    extern __shared__ char smem[];
    const uint32_t sb = smem_u32(smem);
    const int tid = threadIdx.x, wid = tid >> 5, lane = tid & 31;
    const int b = blockIdx.y, pb = blockIdx.x;   // pixel rows pb*8..pb*8+7
    const int f0 = (wid >> 2) * 32;
    const int px0 = (wid & 3) * 64;
    const int g = lane >> 2, tig = lane & 3;

    float d[2][8][4];
#pragma unroll
    for (int i = 0; i < 2; i++)
#pragma unroll
        for (int j = 0; j < 8; j++)
#pragma unroll
            for (int e = 0; e < 4; e++) d[i][j][e] = 0.0f;

    // per-nt B bases (relative to slice origin, before uv shift / kk)
    uint32_t bbase[8];
#pragma unroll
    for (int nt = 0; nt < 8; nt++) {
        int prow = (px0 >> 5) + (nt >> 2);
        int pcol = (nt & 3) * 8 + g;
        bbase[nt] = (uint32_t)((prow * 36 + pcol) * XSP + tig * 4);
    }

    auto load_xslice = [&](int sc) {
        for (int i = tid; i < 5760; i += 512) {
            int r = i / 576, rem = i % 576;
            int c = rem >> 4, seg = rem & 15;
            const float* src = g_xt +
                (((size_t)(b * 34 + pb * 8 + r)) * 36 + c) * 128 + sc * 64 + seg * 4;
            cp16(sb + (uint32_t)((r * 36 + c) * XSP + seg * 16), src);
        }
        CP_COMMIT();
    };

    auto issueA = [&](int ast) {
        const int uv = ast % 9, sc = ast / 9;
        const uint32_t base = sb + XSSZ + (uint32_t)(ast % 3) * ABUF;
#pragma unroll
        for (int i = 0; i < 4; i++) {
            int c2 = i * 512 + tid;
            int row = c2 >> 4, seg = c2 & 15;
            const float* src = g_Wt +
                (((size_t)(b * 9 + uv) * 128 + row)) * 128 + sc * 64 + seg * 4;
            cp16(base + row * XSP + seg * 16, src);
        }
        CP_COMMIT();
    };

    load_xslice(0);
    issueA(0);
    issueA(1);

    for (int ast = 0; ast < 18; ast++) {
        if (ast == 9 || ast == 17) asm volatile("cp.async.wait_group 0;" ::: "memory");
        else                       asm volatile("cp.async.wait_group 1;" ::: "memory");
        __syncthreads();
        if (ast + 2 < 18) issueA(ast + 2);

        const int uv = ast % 9;
        const int u = uv / 3, v = uv - 3 * u;
        const uint32_t uvoff = (uint32_t)((u * 36 + v) * XSP);
        const uint32_t baseA = sb + XSSZ + (uint32_t)(ast % 3) * ABUF;
        // A fragment base: row f0+g, col tig
        const uint32_t abase = baseA + (uint32_t)((f0 + g) * XSP + tig * 4);

#pragma unroll
        for (int kk = 0; kk < 8; kk++) {
            const uint32_t ko = (uint32_t)kk * 32;
            uint32_t a[2][4];
#pragma unroll
            for (int mt = 0; mt < 2; mt++) {
                const uint32_t ab = abase + (uint32_t)(mt * 16 * XSP) + ko;
                a[mt][0] = lds32(ab);
                a[mt][1] = lds32(ab + 8 * XSP);
                a[mt][2] = lds32(ab + 16);
                a[mt][3] = lds32(ab + 8 * XSP + 16);
            }
#pragma unroll
            for (int nt = 0; nt < 8; nt++) {
                uint32_t bfr[2];
                const uint32_t bbv = sb + bbase[nt] + uvoff + ko;
                bfr[0] = lds32(bbv);
                bfr[1] = lds32(bbv + 16);
#pragma unroll
                for (int mt = 0; mt < 2; mt++)
                    mma1688_tf32(d[mt][nt], a[mt], bfr);
            }
        }

        if (ast == 8) {            // chunk boundary: slice 0 fully consumed
            __syncthreads();
            load_xslice(1);
        }
    }

    // ---- epilogue: + residual + bias ----
    const int tc = lane & 3;
#pragma unroll
    for (int i = 0; i < 2; i++) {
        const int fr0 = f0 + i * 16 + g;
        const float bv0 = __ldg(&bias[fr0]);
        const float bv1 = __ldg(&bias[fr0 + 8]);
#pragma unroll
        for (int j = 0; j < 8; j++) {
            const int pix = pb * 256 + px0 + j * 8 + tc * 2;
            {
                size_t o = ((size_t)(b * 128 + fr0)) * 1024 + pix;
                float2 xr = *reinterpret_cast<const float2*>(xin + o);
                float2 w = make_float2(d[i][j][0] + xr.x + bv0,
                                       d[i][j][1] + xr.y + bv0);
                *reinterpret_cast<float2*>(out + o) = w;
            }
            {
                size_t o = ((size_t)(b * 128 + fr0 + 8)) * 1024 + pix;
                float2 xr = *reinterpret_cast<const float2*>(xin + o);
                float2 w = make_float2(d[i][j][2] + xr.x + bv1,
                                       d[i][j][3] + xr.y + bv1);
                *reinterpret_cast<float2*>(out + o) = w;
            }
        }
    }
}

// ===========================================================================
extern "C" void kernel_launch(void* const* d_in, const int* in_sizes, int n_in,
                              void* d_out, int out_size)
{
    (void)in_sizes; (void)n_in; (void)out_size;
    const float* x     = (const float*)d_in[0];
    const float* z     = (const float*)d_in[1];
    const float* dw    = (const float*)d_in[2];
    const float* db    = (const float*)d_in[3];
    const float* gamma = (const float*)d_in[4];
    const float* beta  = (const float*)d_in[5];
    const float* bconv = (const float*)d_in[6];
    float* out = (float*)d_out;

    cudaFuncSetAttribute(hyper_tf32_kernel,
                         cudaFuncAttributeMaxDynamicSharedMemorySize, H2_SMEM);
    cudaFuncSetAttribute(conv_mma_kernel,
                         cudaFuncAttributeMaxDynamicSharedMemorySize, CSMEM);

    hyper_tf32_kernel<<<NB / 256, 512, H2_SMEM>>>(z, dw, db, gamma, beta);
    xprep_kernel<<<dim3(32, BATCH), 256>>>(x);
    wtrans_kernel<<<dim3(16, BATCH), 256>>>();
    conv_mma_kernel<<<dim3(4, BATCH), 512, CSMEM>>>(x, bconv, out);
}

// round 11
// speedup vs baseline: 1.4401x; 1.0712x over previous
#include <cuda_runtime.h>
#include <cuda_bf16.h>
#include <cstdint>

#define CIN   128
#define COUT  128
#define KHW   9
#define NB    (CIN*COUT*KHW)   // 147456
#define ZD    256
#define BATCH 32
#define HW    32
#define HW2   (HW*HW)

// ---------------- scratch (device globals; no allocs allowed) ----------------
__device__ __align__(1024) float g_W2[BATCH * 9 * 128 * 128];      // tf32-rounded (b, uv, s, f)
__device__ __align__(1024) float g_xt[BATCH * 34 * 36 * 128];      // tf32-rounded (b,row,col,s); pad stays 0

// ---------------- helpers ----------------
__device__ __forceinline__ uint32_t smem_u32(const void* p) {
    uint32_t a;
    asm("{ .reg .u64 t; cvta.to.shared.u64 t, %1; cvt.u32.u64 %0, t; }" : "=r"(a) : "l"(p));
    return a;
}
__device__ __forceinline__ void cp16(uint32_t dst, const void* src) {
    asm volatile("cp.async.cg.shared.global [%0], [%1], 16;" :: "r"(dst), "l"(src) : "memory");
}
#define CP_COMMIT() asm volatile("cp.async.commit_group;" ::: "memory")

__device__ __forceinline__ void mma1688_tf32(float* d, const uint32_t* a, const uint32_t* b) {
    asm volatile(
        "mma.sync.aligned.m16n8k8.row.col.f32.tf32.tf32.f32 "
        "{%0,%1,%2,%3}, {%4,%5,%6,%7}, {%8,%9}, {%0,%1,%2,%3};"
        : "+f"(d[0]), "+f"(d[1]), "+f"(d[2]), "+f"(d[3])
        : "r"(a[0]), "r"(a[1]), "r"(a[2]), "r"(a[3]), "r"(b[0]), "r"(b[1]));
}
__device__ __forceinline__ uint32_t cvt_tf32(float f) {
    uint32_t r;
    asm("cvt.rna.tf32.f32 %0, %1;" : "=r"(r) : "f"(f));
    return r;
}
__device__ __forceinline__ uint32_t lds32(uint32_t a) {
    uint32_t r;
    asm volatile("ld.shared.b32 %0, [%1];" : "=r"(r) : "r"(a));
    return r;
}

// ===========================================================================
// Kernel A (tf32, 4-buffer): hyper GEMM + fused BN + DIRECT (b,uv,s,f) output
//   M=32, K=256, N=256 per CTA (576 CTAs), 512 thr, prefetch depth 3.
// smem: A @0 32x268 fp32 (34304B) | B @34304: 4 x (32 x 264 fp32 = 33792B)
// epilogue reuses B region: sOut 32x266 fp32 @H2_RB, tables @H2_RB+40960
// ===========================================================================
#define H2_APW 268
#define H2_BPW 264
#define H2_RB  34304
#define H2_BBUF 33792
#define H2_SMEM 169472

__global__ __launch_bounds__(512, 1) void hyper_tf32_kernel(
    const float* __restrict__ z, const float* __restrict__ dw,
    const float* __restrict__ db, const float* __restrict__ gamma,
    const float* __restrict__ beta)
{
    extern __shared__ char hs[];
    const uint32_t sb = smem_u32(hs);
    const int tid = threadIdx.x, wid = tid >> 5, lane = tid & 31;
    const int n0 = blockIdx.x * 256;
    const int wn0 = wid * 16;
    const int g = lane >> 2, tig = lane & 3;

    auto issue = [&](int s) {
#pragma unroll
        for (int i = 0; i < 4; i++) {
            int chunk = i * 512 + tid;
            int k = chunk >> 6, seg = chunk & 63;
            cp16(sb + H2_RB + (uint32_t)(s & 3) * H2_BBUF + k * (H2_BPW * 4) + seg * 16,
                 dw + (size_t)(s * 32 + k) * NB + n0 + seg * 4);
        }
        CP_COMMIT();
    };
    issue(0);
    issue(1);
    issue(2);

    // A (z) -> tf32 (rna) smem [m=32][k=256]
    {
        const int m = tid >> 4, k0 = (tid & 15) * 16;
        const float4* zsrc = reinterpret_cast<const float4*>(z + m * ZD + k0);
        uint32_t* arow = reinterpret_cast<uint32_t*>(hs) + m * H2_APW + k0;
#pragma unroll
        for (int j = 0; j < 4; j++) {
            float4 v = zsrc[j];
            arow[j * 4 + 0] = cvt_tf32(v.x);
            arow[j * 4 + 1] = cvt_tf32(v.y);
            arow[j * 4 + 2] = cvt_tf32(v.z);
            arow[j * 4 + 3] = cvt_tf32(v.w);
        }
    }

    float d[2][2][4];
#pragma unroll
    for (int mt = 0; mt < 2; mt++)
#pragma unroll
        for (int nt = 0; nt < 2; nt++)
#pragma unroll
            for (int e = 0; e < 4; e++) d[mt][nt][e] = 0.0f;

    const uint32_t abase = sb + (uint32_t)(g * H2_APW + tig) * 4;

    for (int s = 0; s < 8; s++) {
        if (s < 6)      asm volatile("cp.async.wait_group 2;" ::: "memory");
        else if (s == 6) asm volatile("cp.async.wait_group 1;" ::: "memory");
        else             asm volatile("cp.async.wait_group 0;" ::: "memory");
        __syncthreads();
        if (s + 3 < 8) issue(s + 3);

        const uint32_t bbuf = sb + H2_RB + (uint32_t)(s & 3) * H2_BBUF;
#pragma unroll
        for (int kk = 0; kk < 4; kk++) {
            const uint32_t acol = (uint32_t)(s * 32 + kk * 8) * 4;
            uint32_t a[2][4], bfr[2][2];
#pragma unroll
            for (int mt = 0; mt < 2; mt++) {
                const uint32_t ab = abase + (uint32_t)(mt * 16 * H2_APW) * 4 + acol;
                a[mt][0] = lds32(ab);
                a[mt][1] = lds32(ab + (uint32_t)(8 * H2_APW) * 4);
                a[mt][2] = lds32(ab + 16);
                a[mt][3] = lds32(ab + (uint32_t)(8 * H2_APW) * 4 + 16);
            }
#pragma unroll
            for (int nt = 0; nt < 2; nt++) {
                const uint32_t bb = bbuf + (uint32_t)((kk * 8 + tig) * H2_BPW
                                                      + wn0 + nt * 8 + g) * 4;
                bfr[nt][0] = cvt_tf32(__uint_as_float(lds32(bb)));
                bfr[nt][1] = cvt_tf32(__uint_as_float(lds32(bb + (uint32_t)(4 * H2_BPW) * 4)));
            }
#pragma unroll
            for (int mt = 0; mt < 2; mt++)
#pragma unroll
                for (int nt = 0; nt < 2; nt++)
                    mma1688_tf32(d[mt][nt], a[mt], bfr[nt]);
        }
    }

    // ---- epilogue: relu + BN over 32 batch rows (warp-local) ----
    const int jc = n0 + wn0 + 2 * tig;
    float2 db2[2], g2[2], bt2[2];
#pragma unroll
    for (int nt = 0; nt < 2; nt++) {
        db2[nt] = *reinterpret_cast<const float2*>(db + jc + nt * 8);
        g2[nt]  = *reinterpret_cast<const float2*>(gamma + jc + nt * 8);
        bt2[nt] = *reinterpret_cast<const float2*>(beta + jc + nt * 8);
    }
#pragma unroll
    for (int mt = 0; mt < 2; mt++)
#pragma unroll
        for (int nt = 0; nt < 2; nt++) {
            d[mt][nt][0] = fmaxf(d[mt][nt][0] + db2[nt].x, 0.0f);
            d[mt][nt][1] = fmaxf(d[mt][nt][1] + db2[nt].y, 0.0f);
            d[mt][nt][2] = fmaxf(d[mt][nt][2] + db2[nt].x, 0.0f);
            d[mt][nt][3] = fmaxf(d[mt][nt][3] + db2[nt].y, 0.0f);
        }

    float sm[2][2], sq[2][2];
#pragma unroll
    for (int nt = 0; nt < 2; nt++)
#pragma unroll
        for (int c = 0; c < 2; c++) {
            float s1 = d[0][nt][c] + d[0][nt][c + 2] + d[1][nt][c] + d[1][nt][c + 2];
            float q1 = d[0][nt][c] * d[0][nt][c] + d[0][nt][c + 2] * d[0][nt][c + 2]
                     + d[1][nt][c] * d[1][nt][c] + d[1][nt][c + 2] * d[1][nt][c + 2];
#pragma unroll
            for (int o = 4; o < 32; o <<= 1) {
                s1 += __shfl_xor_sync(0xffffffffu, s1, o);
                q1 += __shfl_xor_sync(0xffffffffu, q1, o);
            }
            sm[nt][c] = s1 * (1.0f / 32.0f);
            float var = fmaxf(q1 * (1.0f / 32.0f) - sm[nt][c] * sm[nt][c], 0.0f);
            float gm = (c == 0) ? ((nt == 0) ? g2[0].x : g2[1].x)
                                : ((nt == 0) ? g2[0].y : g2[1].y);
            sq[nt][c] = gm / (sqrtf(var) + 1e-6f);
        }

    // ---- stage normalized tile into smem reorder buffer (reuses B region) ----
    float* sOut = reinterpret_cast<float*>(hs + H2_RB);          // pitch 266 fl
    const int jl0 = wn0 + 2 * tig;
#pragma unroll
    for (int mt = 0; mt < 2; mt++)
#pragma unroll
        for (int nt = 0; nt < 2; nt++) {
            const int jl = jl0 + nt * 8;
            float2 o0 = make_float2((d[mt][nt][0] - sm[nt][0]) * sq[nt][0] + bt2[nt].x,
                                    (d[mt][nt][1] - sm[nt][1]) * sq[nt][1] + bt2[nt].y);
            float2 o1 = make_float2((d[mt][nt][2] - sm[nt][0]) * sq[nt][0] + bt2[nt].x,
                                    (d[mt][nt][3] - sm[nt][1]) * sq[nt][1] + bt2[nt].y);
            *reinterpret_cast<float2*>(&sOut[(mt * 16 + g) * 266 + jl]) = o0;
            *reinterpret_cast<float2*>(&sOut[(mt * 16 + g + 8) * 266 + jl]) = o1;
        }

    // per-tile tables: off[0..9] prefix, fs[uv] first-f  (tbl[0..9], tbl[10..18])
    int* tbl = reinterpret_cast<int*>(hs + H2_RB + 40960);
    const int r0 = n0 % 1152, s0 = n0 / 1152;
    if (tid == 0) {
        int acc = 0;
        for (int uv = 0; uv < 9; uv++) {
            tbl[uv] = acc;
            int cnt = (n0 + 264 - uv) / 9 - (n0 + 8 - uv) / 9;
            tbl[10 + uv] = (r0 + 8 - uv) / 9;
            acc += cnt;
        }
        tbl[9] = acc;   // 256
    }
    __syncthreads();

    // ---- scatter to g_W2 (b,uv,s,f) with f-contiguous runs ----
    for (int e = tid; e < 8192; e += 512) {
        int m = e >> 8, rem = e & 255;
        int uv = 0;
#pragma unroll
        for (int q = 1; q < 9; q++) uv += (rem >= tbl[q]);
        int fi = rem - tbl[uv];
        int fidx = tbl[10 + uv] + fi;
        int s = s0, f = fidx;
        if (fidx >= 128) { f = fidx - 128; s = s0 + 1; }
        int r = f * 9 + uv;
        int jloc = (s - s0) * 1152 + r - r0;
        g_W2[(((size_t)m * 9 + uv) * 128 + s) * 128 + f] = sOut[m * 266 + jloc];
    }
}

// ===========================================================================
// Kernel X: x -> padded channel-last tf32-rounded fp32 (b, row34, col36, s128)
// ===========================================================================
__global__ __launch_bounds__(256) void xprep_kernel(const float* __restrict__ x)
{
    __shared__ float sX[128 * 33];
    const int b = blockIdx.y, p = blockIdx.x, tid = threadIdx.x;
    for (int i = tid; i < 4096; i += 256) {
        int s = i >> 5, q = i & 31;
        sX[s * 33 + q] = x[(((size_t)(b * 128 + s)) * 32 + p) * 32 + q];
    }
    __syncthreads();
    for (int i = tid; i < 4096; i += 256) {
        int s = i & 127, q = i >> 7;
        float v = sX[s * 33 + q];
        size_t o = (((size_t)b * 34 + (p + 1)) * 36 + (q + 1)) * 128 + s;
        g_xt[o] = __uint_as_float(cvt_tf32(v));
    }
}

// ===========================================================================
// Kernel C (tf32): conv GEMM, resident fp32 x-slice + 3-stage A pipeline.
//   A tiles now [s 64][f 128] pitch 136 fl (544B), fed from g_W2 (b,uv,s,f).
// x-slice: [10 r][36 c][68 fl pitch] = 97920 B; A bufs: 3 x 34816
// ===========================================================================
#define XSP    272          // 68 floats
#define XSSZ   97920
#define APB    544          // A row pitch bytes (136 floats)
#define ABUF   34816
#define CSMEM  202368

__global__ __launch_bounds__(512, 1) void conv_mma_kernel(
    const float* __restrict__ xin,
    const float* __restrict__ bias,
    float* __restrict__ out)
{
    extern __shared__ char smem[];
    const uint32_t sb = smem_u32(smem);
    const int tid = threadIdx.x, wid = tid >> 5, lane = tid & 31;
    const int b = blockIdx.y, pb = blockIdx.x;   // pixel rows pb*8..pb*8+7
    const int f0 = (wid >> 2) * 32;
    const int px0 = (wid & 3) * 64;
    const int g = lane >> 2, tig = lane & 3;

    float d[2][8][4];
#pragma unroll
    for (int i = 0; i < 2; i++)
#pragma unroll
        for (int j = 0; j < 8; j++)
#pragma unroll
            for (int e = 0; e < 4; e++) d[i][j][e] = 0.0f;

    uint32_t bbase[8];
#pragma unroll
    for (int nt = 0; nt < 8; nt++) {
        int prow = (px0 >> 5) + (nt >> 2);
        int pcol = (nt & 3) * 8 + g;
        bbase[nt] = (uint32_t)((prow * 36 + pcol) * XSP + tig * 4);
    }

    auto load_xslice = [&](int sc) {
        for (int i = tid; i < 5760; i += 512) {
            int r = i / 576, rem = i % 576;
            int c = rem >> 4, seg = rem & 15;
            const float* src = g_xt +
                (((size_t)(b * 34 + pb * 8 + r)) * 36 + c) * 128 + sc * 64 + seg * 4;
            cp16(sb + (uint32_t)((r * 36 + c) * XSP + seg * 16), src);
        }
        CP_COMMIT();
    };

    auto issueA = [&](int ast) {
        const int uv = ast % 9, sc = ast / 9;
        const uint32_t base = sb + XSSZ + (uint32_t)(ast % 3) * ABUF;
        const float* srcb = g_W2 + ((size_t)(b * 9 + uv) * 128 + sc * 64) * 128;
#pragma unroll
        for (int i = 0; i < 4; i++) {
            int c2 = i * 512 + tid;                 // 0..2047
            int srow = c2 >> 5, seg = c2 & 31;
            cp16(base + (uint32_t)(srow * APB + seg * 16), srcb + srow * 128 + seg * 4);
        }
        CP_COMMIT();
    };

    load_xslice(0);
    issueA(0);
    issueA(1);

    for (int ast = 0; ast < 18; ast++) {
        if (ast == 9 || ast == 17) asm volatile("cp.async.wait_group 0;" ::: "memory");
        else                       asm volatile("cp.async.wait_group 1;" ::: "memory");
        __syncthreads();
        if (ast + 2 < 18) issueA(ast + 2);

        const int uv = ast % 9;
        const int u = uv / 3, v = uv - 3 * u;
        const uint32_t uvoff = (uint32_t)((u * 36 + v) * XSP);
        const uint32_t baseA = sb + XSSZ + (uint32_t)(ast % 3) * ABUF;
        // A fragment base: k-row tig, f col f0+g
        const uint32_t abase0 = baseA + (uint32_t)(tig * APB + (f0 + g) * 4);

#pragma unroll
        for (int kk = 0; kk < 8; kk++) {
            const uint32_t ab = abase0 + (uint32_t)(kk * 8 * APB);
            uint32_t a[2][4];
#pragma unroll
            for (int mt = 0; mt < 2; mt++) {
                const uint32_t abm = ab + (uint32_t)(mt * 64);
                a[mt][0] = lds32(abm);                    // (g,     tig)
                a[mt][1] = lds32(abm + 32);               // (g+8,   tig)
                a[mt][2] = lds32(abm + 4 * APB);          // (g,     tig+4)
                a[mt][3] = lds32(abm + 4 * APB + 32);     // (g+8,   tig+4)
            }
            const uint32_t ko = (uint32_t)kk * 32;
#pragma unroll
            for (int nt = 0; nt < 8; nt++) {
                uint32_t bfr[2];
                const uint32_t bbv = sb + bbase[nt] + uvoff + ko;
                bfr[0] = lds32(bbv);
                bfr[1] = lds32(bbv + 16);
#pragma unroll
                for (int mt = 0; mt < 2; mt++)
                    mma1688_tf32(d[mt][nt], a[mt], bfr);
            }
        }

        if (ast == 8) {            // chunk boundary: slice 0 fully consumed
            __syncthreads();
            load_xslice(1);
        }
    }

    // ---- epilogue: + residual + bias ----
    const int tc = lane & 3;
#pragma unroll
    for (int i = 0; i < 2; i++) {
        const int fr0 = f0 + i * 16 + g;
        const float bv0 = __ldg(&bias[fr0]);
        const float bv1 = __ldg(&bias[fr0 + 8]);
#pragma unroll
        for (int j = 0; j < 8; j++) {
            const int pix = pb * 256 + px0 + j * 8 + tc * 2;
            {
                size_t o = ((size_t)(b * 128 + fr0)) * 1024 + pix;
                float2 xr = *reinterpret_cast<const float2*>(xin + o);
                float2 w = make_float2(d[i][j][0] + xr.x + bv0,
                                       d[i][j][1] + xr.y + bv0);
                *reinterpret_cast<float2*>(out + o) = w;
            }
            {
                size_t o = ((size_t)(b * 128 + fr0 + 8)) * 1024 + pix;
                float2 xr = *reinterpret_cast<const float2*>(xin + o);
                float2 w = make_float2(d[i][j][2] + xr.x + bv1,
                                       d[i][j][3] + xr.y + bv1);
                *reinterpret_cast<float2*>(out + o) = w;
            }
        }
    }
}

// ===========================================================================
extern "C" void kernel_launch(void* const* d_in, const int* in_sizes, int n_in,
                              void* d_out, int out_size)
{
    (void)in_sizes; (void)n_in; (void)out_size;
    const float* x     = (const float*)d_in[0];
    const float* z     = (const float*)d_in[1];
    const float* dw    = (const float*)d_in[2];
    const float* db    = (const float*)d_in[3];
    const float* gamma = (const float*)d_in[4];
    const float* beta  = (const float*)d_in[5];
    const float* bconv = (const float*)d_in[6];
    float* out = (float*)d_out;

    cudaFuncSetAttribute(hyper_tf32_kernel,
                         cudaFuncAttributeMaxDynamicSharedMemorySize, H2_SMEM);
    cudaFuncSetAttribute(conv_mma_kernel,
                         cudaFuncAttributeMaxDynamicSharedMemorySize, CSMEM);

    hyper_tf32_kernel<<<NB / 256, 512, H2_SMEM>>>(z, dw, db, gamma, beta);
    xprep_kernel<<<dim3(32, BATCH), 256>>>(x);
    conv_mma_kernel<<<dim3(4, BATCH), 512, CSMEM>>>(x, bconv, out);
}

// round 12
// speedup vs baseline: 1.5121x; 1.0500x over previous
#include <cuda_runtime.h>
#include <cuda_bf16.h>
#include <cstdint>

#define CIN   128
#define COUT  128
#define KHW   9
#define NB    (CIN*COUT*KHW)   // 147456
#define ZD    256
#define BATCH 32
#define HW    32
#define HW2   (HW*HW)

// ---------------- scratch (device globals; no allocs allowed) ----------------
__device__ __align__(1024) float g_W2[BATCH * 9 * 128 * 128];      // tf32-rounded (b, uv, s, f)
__device__ __align__(1024) float g_xt[BATCH * 34 * 36 * 128];      // tf32-rounded (b,row,col,s); pad stays 0

// ---------------- helpers ----------------
__device__ __forceinline__ uint32_t smem_u32(const void* p) {
    uint32_t a;
    asm("{ .reg .u64 t; cvta.to.shared.u64 t, %1; cvt.u32.u64 %0, t; }" : "=r"(a) : "l"(p));
    return a;
}
__device__ __forceinline__ void cp16(uint32_t dst, const void* src) {
    asm volatile("cp.async.cg.shared.global [%0], [%1], 16;" :: "r"(dst), "l"(src) : "memory");
}
#define CP_COMMIT() asm volatile("cp.async.commit_group;" ::: "memory")

__device__ __forceinline__ void mma1688_tf32(float* d, const uint32_t* a, const uint32_t* b) {
    asm volatile(
        "mma.sync.aligned.m16n8k8.row.col.f32.tf32.tf32.f32 "
        "{%0,%1,%2,%3}, {%4,%5,%6,%7}, {%8,%9}, {%0,%1,%2,%3};"
        : "+f"(d[0]), "+f"(d[1]), "+f"(d[2]), "+f"(d[3])
        : "r"(a[0]), "r"(a[1]), "r"(a[2]), "r"(a[3]), "r"(b[0]), "r"(b[1]));
}
__device__ __forceinline__ uint32_t cvt_tf32(float f) {
    uint32_t r;
    asm("cvt.rna.tf32.f32 %0, %1;" : "=r"(r) : "f"(f));
    return r;
}
__device__ __forceinline__ uint32_t lds32(uint32_t a) {
    uint32_t r;
    asm volatile("ld.shared.b32 %0, [%1];" : "=r"(r) : "r"(a));
    return r;
}

// ===========================================================================
// Kernel A (tf32, 16 stages x K16, 4 buffers): hyper GEMM + fused BN +
// DIRECT (b,uv,s,f) output. 2 CTAs/SM (101.9KB smem, 64 regs).
// smem: A @0 32x268 fp32 (34304B) | B @34304: 4 x (16 x 264 fp32 = 16896B)
// epilogue reuses B region: sOut 32x266 fp32 @H2_RB, tables @H2_RB+40960
// ===========================================================================
#define H2_APW 268
#define H2_BPW 264
#define H2_RB  34304
#define H2_BBUF 16896
#define H2_SMEM 101888

__global__ __launch_bounds__(512, 2) void hyper_tf32_kernel(
    const float* __restrict__ z, const float* __restrict__ dw,
    const float* __restrict__ db, const float* __restrict__ gamma,
    const float* __restrict__ beta)
{
    extern __shared__ char hs[];
    const uint32_t sb = smem_u32(hs);
    const int tid = threadIdx.x, wid = tid >> 5, lane = tid & 31;
    const int n0 = blockIdx.x * 256;
    const int wn0 = wid * 16;
    const int g = lane >> 2, tig = lane & 3;

    auto issue = [&](int s) {
#pragma unroll
        for (int i = 0; i < 2; i++) {
            int chunk = i * 512 + tid;              // 0..1023
            int k = chunk >> 6, seg = chunk & 63;
            cp16(sb + H2_RB + (uint32_t)(s & 3) * H2_BBUF + k * (H2_BPW * 4) + seg * 16,
                 dw + (size_t)(s * 16 + k) * NB + n0 + seg * 4);
        }
        CP_COMMIT();
    };
    issue(0);
    issue(1);
    issue(2);

    // A (z) -> tf32 (rna) smem [m=32][k=256]
    {
        const int m = tid >> 4, k0 = (tid & 15) * 16;
        const float4* zsrc = reinterpret_cast<const float4*>(z + m * ZD + k0);
        uint32_t* arow = reinterpret_cast<uint32_t*>(hs) + m * H2_APW + k0;
#pragma unroll
        for (int j = 0; j < 4; j++) {
            float4 v = zsrc[j];
            arow[j * 4 + 0] = cvt_tf32(v.x);
            arow[j * 4 + 1] = cvt_tf32(v.y);
            arow[j * 4 + 2] = cvt_tf32(v.z);
            arow[j * 4 + 3] = cvt_tf32(v.w);
        }
    }

    float d[2][2][4];
#pragma unroll
    for (int mt = 0; mt < 2; mt++)
#pragma unroll
        for (int nt = 0; nt < 2; nt++)
#pragma unroll
            for (int e = 0; e < 4; e++) d[mt][nt][e] = 0.0f;

    const uint32_t abase = sb + (uint32_t)(g * H2_APW + tig) * 4;

    for (int s = 0; s < 16; s++) {
        if (s < 14)      asm volatile("cp.async.wait_group 2;" ::: "memory");
        else if (s == 14) asm volatile("cp.async.wait_group 1;" ::: "memory");
        else              asm volatile("cp.async.wait_group 0;" ::: "memory");
        __syncthreads();
        if (s + 3 < 16) issue(s + 3);

        const uint32_t bbuf = sb + H2_RB + (uint32_t)(s & 3) * H2_BBUF;
#pragma unroll
        for (int kk = 0; kk < 2; kk++) {
            const uint32_t acol = (uint32_t)(s * 16 + kk * 8) * 4;
            uint32_t a[2][4], bfr[2][2];
#pragma unroll
            for (int mt = 0; mt < 2; mt++) {
                const uint32_t ab = abase + (uint32_t)(mt * 16 * H2_APW) * 4 + acol;
                a[mt][0] = lds32(ab);
                a[mt][1] = lds32(ab + (uint32_t)(8 * H2_APW) * 4);
                a[mt][2] = lds32(ab + 16);
                a[mt][3] = lds32(ab + (uint32_t)(8 * H2_APW) * 4 + 16);
            }
#pragma unroll
            for (int nt = 0; nt < 2; nt++) {
                const uint32_t bb = bbuf + (uint32_t)((kk * 8 + tig) * H2_BPW
                                                      + wn0 + nt * 8 + g) * 4;
                bfr[nt][0] = cvt_tf32(__uint_as_float(lds32(bb)));
                bfr[nt][1] = cvt_tf32(__uint_as_float(lds32(bb + (uint32_t)(4 * H2_BPW) * 4)));
            }
#pragma unroll
            for (int mt = 0; mt < 2; mt++)
#pragma unroll
                for (int nt = 0; nt < 2; nt++)
                    mma1688_tf32(d[mt][nt], a[mt], bfr[nt]);
        }
    }

    // ---- epilogue: relu + BN over 32 batch rows (warp-local) ----
    const int jc = n0 + wn0 + 2 * tig;
    float2 db2[2], g2[2], bt2[2];
#pragma unroll
    for (int nt = 0; nt < 2; nt++) {
        db2[nt] = *reinterpret_cast<const float2*>(db + jc + nt * 8);
        g2[nt]  = *reinterpret_cast<const float2*>(gamma + jc + nt * 8);
        bt2[nt] = *reinterpret_cast<const float2*>(beta + jc + nt * 8);
    }
#pragma unroll
    for (int mt = 0; mt < 2; mt++)
#pragma unroll
        for (int nt = 0; nt < 2; nt++) {
            d[mt][nt][0] = fmaxf(d[mt][nt][0] + db2[nt].x, 0.0f);
            d[mt][nt][1] = fmaxf(d[mt][nt][1] + db2[nt].y, 0.0f);
            d[mt][nt][2] = fmaxf(d[mt][nt][2] + db2[nt].x, 0.0f);
            d[mt][nt][3] = fmaxf(d[mt][nt][3] + db2[nt].y, 0.0f);
        }

    float sm[2][2], sq[2][2];
#pragma unroll
    for (int nt = 0; nt < 2; nt++)
#pragma unroll
        for (int c = 0; c < 2; c++) {
            float s1 = d[0][nt][c] + d[0][nt][c + 2] + d[1][nt][c] + d[1][nt][c + 2];
            float q1 = d[0][nt][c] * d[0][nt][c] + d[0][nt][c + 2] * d[0][nt][c + 2]
                     + d[1][nt][c] * d[1][nt][c] + d[1][nt][c + 2] * d[1][nt][c + 2];
#pragma unroll
            for (int o = 4; o < 32; o <<= 1) {
                s1 += __shfl_xor_sync(0xffffffffu, s1, o);
                q1 += __shfl_xor_sync(0xffffffffu, q1, o);
            }
            sm[nt][c] = s1 * (1.0f / 32.0f);
            float var = fmaxf(q1 * (1.0f / 32.0f) - sm[nt][c] * sm[nt][c], 0.0f);
            float gm = (c == 0) ? ((nt == 0) ? g2[0].x : g2[1].x)
                                : ((nt == 0) ? g2[0].y : g2[1].y);
            sq[nt][c] = gm / (sqrtf(var) + 1e-6f);
        }

    // ---- stage normalized tile into smem reorder buffer (reuses B region) ----
    float* sOut = reinterpret_cast<float*>(hs + H2_RB);          // pitch 266 fl
    const int jl0 = wn0 + 2 * tig;
#pragma unroll
    for (int mt = 0; mt < 2; mt++)
#pragma unroll
        for (int nt = 0; nt < 2; nt++) {
            const int jl = jl0 + nt * 8;
            float2 o0 = make_float2((d[mt][nt][0] - sm[nt][0]) * sq[nt][0] + bt2[nt].x,
                                    (d[mt][nt][1] - sm[nt][1]) * sq[nt][1] + bt2[nt].y);
            float2 o1 = make_float2((d[mt][nt][2] - sm[nt][0]) * sq[nt][0] + bt2[nt].x,
                                    (d[mt][nt][3] - sm[nt][1]) * sq[nt][1] + bt2[nt].y);
            *reinterpret_cast<float2*>(&sOut[(mt * 16 + g) * 266 + jl]) = o0;
            *reinterpret_cast<float2*>(&sOut[(mt * 16 + g + 8) * 266 + jl]) = o1;
        }

    // per-tile tables: off[0..9] prefix, fs[uv] first-f  (tbl[0..9], tbl[10..18])
    int* tbl = reinterpret_cast<int*>(hs + H2_RB + 40960);
    const int r0 = n0 % 1152, s0 = n0 / 1152;
    if (tid == 0) {
        int acc = 0;
        for (int uv = 0; uv < 9; uv++) {
            tbl[uv] = acc;
            int cnt = (n0 + 264 - uv) / 9 - (n0 + 8 - uv) / 9;
            tbl[10 + uv] = (r0 + 8 - uv) / 9;
            acc += cnt;
        }
        tbl[9] = acc;   // 256
    }
    __syncthreads();

    // ---- scatter to g_W2 (b,uv,s,f) with f-contiguous runs ----
    for (int e = tid; e < 8192; e += 512) {
        int m = e >> 8, rem = e & 255;
        int uv = 0;
#pragma unroll
        for (int q = 1; q < 9; q++) uv += (rem >= tbl[q]);
        int fi = rem - tbl[uv];
        int fidx = tbl[10 + uv] + fi;
        int s = s0, f = fidx;
        if (fidx >= 128) { f = fidx - 128; s = s0 + 1; }
        int r = f * 9 + uv;
        int jloc = (s - s0) * 1152 + r - r0;
        g_W2[(((size_t)m * 9 + uv) * 128 + s) * 128 + f] = sOut[m * 266 + jloc];
    }
}

// ===========================================================================
// Kernel X: x -> padded channel-last tf32-rounded fp32 (b, row34, col36, s128)
// ===========================================================================
__global__ __launch_bounds__(256) void xprep_kernel(const float* __restrict__ x)
{
    __shared__ float sX[128 * 33];
    const int b = blockIdx.y, p = blockIdx.x, tid = threadIdx.x;
    for (int i = tid; i < 4096; i += 256) {
        int s = i >> 5, q = i & 31;
        sX[s * 33 + q] = x[(((size_t)(b * 128 + s)) * 32 + p) * 32 + q];
    }
    __syncthreads();
    for (int i = tid; i < 4096; i += 256) {
        int s = i & 127, q = i >> 7;
        float v = sX[s * 33 + q];
        size_t o = (((size_t)b * 34 + (p + 1)) * 36 + (q + 1)) * 128 + s;
        g_xt[o] = __uint_as_float(cvt_tf32(v));
    }
}

// ===========================================================================
// Kernel C (tf32): conv GEMM, resident fp32 x-slice + 3-stage A pipeline.
//   A tiles [s 64][f 128] pitch 136 fl, fed from g_W2 (b,uv,s,f).  (proven R11)
// ===========================================================================
#define XSP    272          // 68 floats
#define XSSZ   97920
#define APB    544          // A row pitch bytes (136 floats)
#define ABUF   34816
#define CSMEM  202368

__global__ __launch_bounds__(512, 1) void conv_mma_kernel(
    const float* __restrict__ xin,
    const float* __restrict__ bias,
    float* __restrict__ out)
{
    extern __shared__ char smem[];
    const uint32_t sb = smem_u32(smem);
    const int tid = threadIdx.x, wid = tid >> 5, lane = tid & 31;
    const int b = blockIdx.y, pb = blockIdx.x;   // pixel rows pb*8..pb*8+7
    const int f0 = (wid >> 2) * 32;
    const int px0 = (wid & 3) * 64;
    const int g = lane >> 2, tig = lane & 3;

    float d[2][8][4];
#pragma unroll
    for (int i = 0; i < 2; i++)
#pragma unroll
        for (int j = 0; j < 8; j++)
#pragma unroll
            for (int e = 0; e < 4; e++) d[i][j][e] = 0.0f;

    uint32_t bbase[8];
#pragma unroll
    for (int nt = 0; nt < 8; nt++) {
        int prow = (px0 >> 5) + (nt >> 2);
        int pcol = (nt & 3) * 8 + g;
        bbase[nt] = (uint32_t)((prow * 36 + pcol) * XSP + tig * 4);
    }

    auto load_xslice = [&](int sc) {
        for (int i = tid; i < 5760; i += 512) {
            int r = i / 576, rem = i % 576;
            int c = rem >> 4, seg = rem & 15;
            const float* src = g_xt +
                (((size_t)(b * 34 + pb * 8 + r)) * 36 + c) * 128 + sc * 64 + seg * 4;
            cp16(sb + (uint32_t)((r * 36 + c) * XSP + seg * 16), src);
        }
        CP_COMMIT();
    };

    auto issueA = [&](int ast) {
        const int uv = ast % 9, sc = ast / 9;
        const uint32_t base = sb + XSSZ + (uint32_t)(ast % 3) * ABUF;
        const float* srcb = g_W2 + ((size_t)(b * 9 + uv) * 128 + sc * 64) * 128;
#pragma unroll
        for (int i = 0; i < 4; i++) {
            int c2 = i * 512 + tid;                 // 0..2047
            int srow = c2 >> 5, seg = c2 & 31;
            cp16(base + (uint32_t)(srow * APB + seg * 16), srcb + srow * 128 + seg * 4);
        }
        CP_COMMIT();
    };

    load_xslice(0);
    issueA(0);
    issueA(1);

    for (int ast = 0; ast < 18; ast++) {
        if (ast == 9 || ast == 17) asm volatile("cp.async.wait_group 0;" ::: "memory");
        else                       asm volatile("cp.async.wait_group 1;" ::: "memory");
        __syncthreads();
        if (ast + 2 < 18) issueA(ast + 2);

        const int uv = ast % 9;
        const int u = uv / 3, v = uv - 3 * u;
        const uint32_t uvoff = (uint32_t)((u * 36 + v) * XSP);
        const uint32_t baseA = sb + XSSZ + (uint32_t)(ast % 3) * ABUF;
        const uint32_t abase0 = baseA + (uint32_t)(tig * APB + (f0 + g) * 4);

#pragma unroll
        for (int kk = 0; kk < 8; kk++) {
            const uint32_t ab = abase0 + (uint32_t)(kk * 8 * APB);
            uint32_t a[2][4];
#pragma unroll
            for (int mt = 0; mt < 2; mt++) {
                const uint32_t abm = ab + (uint32_t)(mt * 64);
                a[mt][0] = lds32(abm);
                a[mt][1] = lds32(abm + 32);
                a[mt][2] = lds32(abm + 4 * APB);
                a[mt][3] = lds32(abm + 4 * APB + 32);
            }
            const uint32_t ko = (uint32_t)kk * 32;
#pragma unroll
            for (int nt = 0; nt < 8; nt++) {
                uint32_t bfr[2];
                const uint32_t bbv = sb + bbase[nt] + uvoff + ko;
                bfr[0] = lds32(bbv);
                bfr[1] = lds32(bbv + 16);
#pragma unroll
                for (int mt = 0; mt < 2; mt++)
                    mma1688_tf32(d[mt][nt], a[mt], bfr);
            }
        }

        if (ast == 8) {
            __syncthreads();
            load_xslice(1);
        }
    }

    // ---- epilogue: + residual + bias ----
    const int tc = lane & 3;
#pragma unroll
    for (int i = 0; i < 2; i++) {
        const int fr0 = f0 + i * 16 + g;
        const float bv0 = __ldg(&bias[fr0]);
        const float bv1 = __ldg(&bias[fr0 + 8]);
#pragma unroll
        for (int j = 0; j < 8; j++) {
            const int pix = pb * 256 + px0 + j * 8 + tc * 2;
            {
                size_t o = ((size_t)(b * 128 + fr0)) * 1024 + pix;
                float2 xr = *reinterpret_cast<const float2*>(xin + o);
                float2 w = make_float2(d[i][j][0] + xr.x + bv0,
                                       d[i][j][1] + xr.y + bv0);
                *reinterpret_cast<float2*>(out + o) = w;
            }
            {
                size_t o = ((size_t)(b * 128 + fr0 + 8)) * 1024 + pix;
                float2 xr = *reinterpret_cast<const float2*>(xin + o);
                float2 w = make_float2(d[i][j][2] + xr.x + bv1,
                                       d[i][j][3] + xr.y + bv1);
                *reinterpret_cast<float2*>(out + o) = w;
            }
        }
    }
}

// ===========================================================================
extern "C" void kernel_launch(void* const* d_in, const int* in_sizes, int n_in,
                              void* d_out, int out_size)
{
    (void)in_sizes; (void)n_in; (void)out_size;
    const float* x     = (const float*)d_in[0];
    const float* z     = (const float*)d_in[1];
    const float* dw    = (const float*)d_in[2];
    const float* db    = (const float*)d_in[3];
    const float* gamma = (const float*)d_in[4];
    const float* beta  = (const float*)d_in[5];
    const float* bconv = (const float*)d_in[6];
    float* out = (float*)d_out;

    cudaFuncSetAttribute(hyper_tf32_kernel,
                         cudaFuncAttributeMaxDynamicSharedMemorySize, H2_SMEM);
    cudaFuncSetAttribute(conv_mma_kernel,
                         cudaFuncAttributeMaxDynamicSharedMemorySize, CSMEM);

    hyper_tf32_kernel<<<NB / 256, 512, H2_SMEM>>>(z, dw, db, gamma, beta);
    xprep_kernel<<<dim3(32, BATCH), 256>>>(x);
    conv_mma_kernel<<<dim3(4, BATCH), 512, CSMEM>>>(x, bconv, out);
}